// round 1
// baseline (speedup 1.0000x reference)
#include <cuda_runtime.h>
#include <math.h>

// ---------------- problem constants ----------------
#define NATOMS 16384
#define NMOL   512
#define APM    32
#define EPM    992          // 32*31 edges per molecule
#define FDIM   128
#define NRBF   20
#define FH     64
#define NLAY   3
#define PI_F   3.14159265358979f
#define CUT    5.0f
#define LOG2_F 0.6931471805599453f

static const long long ETOT = (long long)NMOL * EPM;          // 507904
static const size_t EF  = (size_t)ETOT * FDIM;                // 65,011,712
static const size_t NF  = (size_t)NATOMS * FDIM;              // 2,097,152
static const size_t NH  = (size_t)NATOMS * FH;

// ---------------- scratch (device globals; no allocation) ----------------
__device__ float g_x    [NF];            // running x
__device__ float g_h    [3 * NF];        // h per layer (needed in bwd)
__device__ float g_sig2 [3 * NF];        // sigmoid of f2out pre-act per layer
__device__ float g_Wf   [3 * EF];        // edge filters per layer
__device__ float g_s1   [3 * EF];        // sigmoid of filter pre-act per layer
__device__ float g_t1   [EF];            // temp [E,F]
__device__ float g_gWf  [EF];            // temp [E,F]
__device__ float g_gpre1[EF];            // temp [E,F]
__device__ float g_grbf [NRBF * 507904]; // temp [E,20]
__device__ float g_rbf  [NRBF * 507904]; // rbf  [E,20]
__device__ float g_d    [507904];
__device__ float g_fcut [507904];
__device__ float g_gd   [507904];
__device__ float g_agg  [NF];
__device__ float g_tmp  [NF];
__device__ float g_gx   [NF];
__device__ float g_gh   [NF];
__device__ float g_ga   [NF];
__device__ float g_tH   [NH];
__device__ float g_sigH [NH];

// ---------------- generic tiled SGEMM ----------------
// C[M,NO] = act( A[M,K] @ B (+bias) (+skip) ) (*cmul)
// TRANSB: B stored [NO,K] row-major (i.e. computes A @ B^T of a [NO,K] matrix)
// ACT==1: C = ssp(v), Sig = sigmoid(v)
template<int BM,int BN,int BK,int TM,int TN,bool TRANSB,int ACT,bool HB,bool HS,bool HC>
__global__ __launch_bounds__(256) void gemm_k(
    const float* __restrict__ A, const float* __restrict__ B,
    const float* __restrict__ bias, const float* __restrict__ skip,
    const float* __restrict__ cmul, float* __restrict__ C,
    float* __restrict__ Sig, int M, int K, int NO)
{
    constexpr int NTH = (BM/TM)*(BN/TN);
    static_assert(NTH == 256, "thread count");
    __shared__ float As[BK][BM+4];
    __shared__ float Bs[BK][BN+4];
    const int tid  = threadIdx.x;
    const int row0 = blockIdx.x * BM;
    const int col0 = blockIdx.y * BN;
    const int tcol = tid % (BN/TN);
    const int trow = tid / (BN/TN);
    float acc[TM][TN];
    #pragma unroll
    for (int m=0;m<TM;m++)
        #pragma unroll
        for (int n=0;n<TN;n++) acc[m][n] = 0.f;

    for (int k0 = 0; k0 < K; k0 += BK) {
        #pragma unroll
        for (int s=0; s<(BM*BK)/NTH; s++) {
            int idx = tid + s*NTH;
            int r = idx / BK, kk = idx % BK;
            int gr = row0 + r, gk = k0 + kk;
            As[kk][r] = (gr < M && gk < K) ? A[(size_t)gr*K + gk] : 0.f;
        }
        #pragma unroll
        for (int s=0; s<(BN*BK)/NTH; s++) {
            int idx = tid + s*NTH;
            float v; int kk, c;
            if (TRANSB) {
                c = idx / BK; kk = idx % BK;
                int gc = col0 + c, gk = k0 + kk;
                v = (gc < NO && gk < K) ? B[(size_t)gc*K + gk] : 0.f;
            } else {
                kk = idx / BN; c = idx % BN;
                int gc = col0 + c, gk = k0 + kk;
                v = (gc < NO && gk < K) ? B[(size_t)gk*NO + gc] : 0.f;
            }
            Bs[kk][c] = v;
        }
        __syncthreads();
        #pragma unroll
        for (int kk=0; kk<BK; kk++) {
            float a[TM], b[TN];
            #pragma unroll
            for (int m=0;m<TM;m+=4) {
                float4 t = *(const float4*)&As[kk][trow*TM+m];
                a[m]=t.x; a[m+1]=t.y; a[m+2]=t.z; a[m+3]=t.w;
            }
            #pragma unroll
            for (int n=0;n<TN;n+=4) {
                float4 t = *(const float4*)&Bs[kk][tcol*TN+n];
                b[n]=t.x; b[n+1]=t.y; b[n+2]=t.z; b[n+3]=t.w;
            }
            #pragma unroll
            for (int m=0;m<TM;m++)
                #pragma unroll
                for (int n=0;n<TN;n++)
                    acc[m][n] = fmaf(a[m], b[n], acc[m][n]);
        }
        __syncthreads();
    }

    #pragma unroll
    for (int m=0;m<TM;m++) {
        int r = row0 + trow*TM + m;
        if (r >= M) continue;
        #pragma unroll
        for (int n=0;n<TN;n++) {
            int c = col0 + tcol*TN + n;
            if (c >= NO) continue;
            float v = acc[m][n];
            if (HB) v += bias[c];
            if (HS) v += skip[(size_t)r*NO + c];
            if (HC) v *= cmul[(size_t)r*NO + c];
            if (ACT == 1) {
                float sg = 1.f / (1.f + expf(-v));
                Sig[(size_t)r*NO + c] = sg;
                v = fmaxf(v, 0.f) + log1pf(expf(-fabsf(v))) - LOG2_F; // ssp
            }
            C[(size_t)r*NO + c] = v;
        }
    }
}

// ---------------- edge geometry ----------------
__global__ void edge_geom_k(const float* __restrict__ pos,
                            const int* __restrict__ ii, const int* __restrict__ jj,
                            float* __restrict__ dd, float* __restrict__ fc,
                            float* __restrict__ rbf)
{
    long long e = (long long)blockIdx.x * blockDim.x + threadIdx.x;
    if (e >= ETOT) return;
    int i = ii[e], j = jj[e];
    float rx = pos[j*3+0]-pos[i*3+0];
    float ry = pos[j*3+1]-pos[i*3+1];
    float rz = pos[j*3+2]-pos[i*3+2];
    float d = sqrtf(rx*rx+ry*ry+rz*rz + 1e-12f);
    dd[e] = d;
    fc[e] = (d < CUT) ? 0.5f*(cosf(PI_F*d/CUT)+1.f) : 0.f;
    const float DELTA = CUT / (NRBF-1);
    const float CO = -0.5f / (DELTA*DELTA);
    #pragma unroll
    for (int k=0;k<NRBF;k++) {
        float t = d - k*DELTA;
        rbf[(size_t)e*NRBF + k] = expf(CO*t*t);
    }
}

__global__ void gather_emb_k(const float* __restrict__ emb, const int* __restrict__ Z,
                             float* __restrict__ x)
{
    int idx = blockIdx.x*256 + threadIdx.x;
    if (idx >= NATOMS*FDIM) return;
    int n = idx >> 7, f = idx & 127;
    x[idx] = emb[(size_t)Z[n]*FDIM + f];
}

// ---------------- per-molecule message aggregation ----------------
__global__ __launch_bounds__(256) void msg_agg_k(
    const float* __restrict__ h, const float* __restrict__ Wf,
    const float* __restrict__ fcut, const int* __restrict__ jj,
    float* __restrict__ agg)
{
    __shared__ float h_s[APM*FDIM];
    __shared__ float fc_s[EPM];
    __shared__ int   jl_s[EPM];
    int mol = blockIdx.x, tid = threadIdx.x;
    int abase = mol*APM;
    size_t ebase = (size_t)mol*EPM;
    for (int t=tid; t<APM*FDIM; t+=256) h_s[t] = h[(size_t)abase*FDIM + t];
    for (int t=tid; t<EPM; t+=256) { fc_s[t] = fcut[ebase+t]; jl_s[t] = jj[ebase+t] - abase; }
    __syncthreads();
    int f = tid & 127, ih = tid >> 7;
    for (int i2=0; i2<16; i2++) {
        int i = 2*i2 + ih;
        float acc = 0.f;
        const float* wp = Wf + (ebase + (size_t)i*31)*FDIM + f;
        for (int c=0; c<31; c++) {
            int el = i*31 + c;
            acc = fmaf(h_s[jl_s[el]*FDIM + f] * fc_s[el], wp[(size_t)c*FDIM], acc);
        }
        agg[(size_t)(abase+i)*FDIM + f] = acc;
    }
}

// ---------------- per-molecule edge backward ----------------
__global__ __launch_bounds__(256) void edge_bwd_k(
    const float* __restrict__ gragg, const float* __restrict__ h,
    const float* __restrict__ Wf, const float* __restrict__ fcut,
    const float* __restrict__ dd, float* __restrict__ gWf,
    float* __restrict__ gradh, float* __restrict__ gd)
{
    __shared__ float h_s[APM*FDIM];
    __shared__ float ga_s[APM*FDIM];
    __shared__ float fc_s[EPM];
    __shared__ float gd_s[EPM];
    int mol = blockIdx.x, tid = threadIdx.x;
    int abase = mol*APM;
    size_t ebase = (size_t)mol*EPM;
    for (int t=tid; t<APM*FDIM; t+=256) {
        h_s[t]  = h[(size_t)abase*FDIM + t];
        ga_s[t] = gragg[(size_t)abase*FDIM + t];
    }
    for (int t=tid; t<EPM; t+=256) { fc_s[t] = fcut[ebase+t]; gd_s[t] = 0.f; }
    __syncthreads();
    int f = tid & 127, jh = tid >> 7, lane = tid & 31;
    for (int j2=0; j2<16; j2++) {
        int j = 2*j2 + jh;
        float hj = h_s[j*FDIM + f];
        float ghacc = 0.f;
        for (int ii=0; ii<32; ii++) {
            if (ii == j) continue;
            int el = ii*31 + ((j < ii) ? j : j-1);
            float fc = fc_s[el];
            float ga = ga_s[ii*FDIM + f];
            float wf = Wf[(ebase+el)*FDIM + f];
            ghacc = fmaf(ga*fc, wf, ghacc);
            gWf[(ebase+el)*FDIM + f] = ga*hj*fc;
            float term = ga*hj*wf;
            #pragma unroll
            for (int o=16;o>0;o>>=1) term += __shfl_xor_sync(0xffffffffu, term, o);
            if (lane == 0) atomicAdd(&gd_s[el], term);
        }
        gradh[(size_t)(abase+j)*FDIM + f] = ghacc;
    }
    __syncthreads();
    for (int el=tid; el<EPM; el+=256) {
        float dv = dd[ebase+el];
        float dfc = (dv < CUT) ? (-0.5f*PI_F/CUT)*sinf(PI_F*dv/CUT) : 0.f;
        gd[ebase+el] += gd_s[el]*dfc;
    }
}

// ---------------- grad_d contribution from rbf path ----------------
__global__ void rbf_gd_k(const float* __restrict__ grbf, const float* __restrict__ rbf,
                         const float* __restrict__ dd, float* __restrict__ gd)
{
    long long e = (long long)blockIdx.x*256 + threadIdx.x;
    if (e >= ETOT) return;
    float dv = dd[e];
    const float DELTA = CUT / (NRBF-1);
    const float C2 = -1.0f / (DELTA*DELTA); // 2*coeff
    float s = 0.f;
    #pragma unroll
    for (int k=0;k<NRBF;k++)
        s = fmaf(grbf[(size_t)e*NRBF+k]*rbf[(size_t)e*NRBF+k], C2*(dv - k*DELTA), s);
    gd[e] += s;
}

// ---------------- head: energy per molecule ----------------
__global__ __launch_bounds__(256) void head_energy_k(
    const float* __restrict__ tH, const float* __restrict__ w2,
    const float* __restrict__ b2, float* __restrict__ out_energy)
{
    __shared__ float es[APM];
    int mol = blockIdx.x, tid = threadIdx.x;
    int w = tid >> 5, lane = tid & 31;
    for (int a4=0; a4<4; a4++) {
        int a = w*4 + a4;
        size_t n = (size_t)mol*APM + a;
        float v = tH[n*FH+lane]*w2[lane] + tH[n*FH+lane+32]*w2[lane+32];
        #pragma unroll
        for (int o=16;o>0;o>>=1) v += __shfl_xor_sync(0xffffffffu, v, o);
        if (lane == 0) es[a] = v + b2[0];
    }
    __syncthreads();
    if (tid == 0) {
        float s = 0.f;
        for (int a=0;a<APM;a++) s += es[a];
        out_energy[mol] = s;
    }
}

__global__ void headgrad_k(const float* __restrict__ sigH, const float* __restrict__ w2,
                           float* __restrict__ gp)
{
    int idx = blockIdx.x*256 + threadIdx.x;
    if (idx >= NATOMS*FH) return;
    gp[idx] = sigH[idx]*w2[idx & 63];
}

// ---------------- final: grad_pos, clip, write action ----------------
__global__ __launch_bounds__(256) void action_k(
    const float* __restrict__ pos, const float* __restrict__ gd,
    const float* __restrict__ dd, const int* __restrict__ ii,
    const int* __restrict__ jj, float* __restrict__ out)
{
    __shared__ float gp[APM*3];
    __shared__ float nrm[APM];
    __shared__ float coef_s;
    int mol = blockIdx.x, tid = threadIdx.x;
    int abase = mol*APM;
    size_t ebase = (size_t)mol*EPM;
    if (tid < APM*3) gp[tid] = 0.f;
    __syncthreads();
    for (int el=tid; el<EPM; el+=256) {
        size_t e = ebase + el;
        int i = ii[e], j = jj[e];
        float rx = pos[j*3+0]-pos[i*3+0];
        float ry = pos[j*3+1]-pos[i*3+1];
        float rz = pos[j*3+2]-pos[i*3+2];
        float g = gd[e] / dd[e];
        int jl = (j-abase)*3, il = (i-abase)*3;
        atomicAdd(&gp[jl+0],  g*rx); atomicAdd(&gp[jl+1],  g*ry); atomicAdd(&gp[jl+2],  g*rz);
        atomicAdd(&gp[il+0], -g*rx); atomicAdd(&gp[il+1], -g*ry); atomicAdd(&gp[il+2], -g*rz);
    }
    __syncthreads();
    if (tid < APM) {
        float ax = gp[tid*3+0], ay = gp[tid*3+1], az = gp[tid*3+2];
        nrm[tid] = sqrtf(ax*ax + ay*ay + az*az);
    }
    __syncthreads();
    if (tid == 0) {
        float mx = 0.f;
        for (int a=0;a<APM;a++) mx = fmaxf(mx, nrm[a]);
        coef_s = fminf(1.0f / fmaxf(mx, 1e-8f), 1.0f);
    }
    __syncthreads();
    float cf = coef_s;
    for (int t=tid; t<APM*3; t+=256)
        out[(size_t)abase*3 + t] = -gp[t]*cf;
}

// ---------------- host ----------------
extern "C" void kernel_launch(void* const* d_in, const int* in_sizes, int n_in,
                              void* d_out, int out_size)
{
    const float* positions = (const float*)d_in[0];
    const float* emb       = (const float*)d_in[1];
    const float* in2f_W    = (const float*)d_in[2];
    const float* filt_W1   = (const float*)d_in[3];
    const float* filt_b1   = (const float*)d_in[4];
    const float* filt_W2   = (const float*)d_in[5];
    const float* filt_b2   = (const float*)d_in[6];
    const float* f2_W1     = (const float*)d_in[7];
    const float* f2_b1     = (const float*)d_in[8];
    const float* f2_W2     = (const float*)d_in[9];
    const float* f2_b2     = (const float*)d_in[10];
    const float* aw_W1     = (const float*)d_in[11];
    const float* aw_b1     = (const float*)d_in[12];
    const float* aw_W2     = (const float*)d_in[13];
    const float* aw_b2     = (const float*)d_in[14];
    const int*   Z         = (const int*)d_in[15];
    const int*   idx_i     = (const int*)d_in[16];
    const int*   idx_j     = (const int*)d_in[17];
    float* out = (float*)d_out;

    float *p_x,*p_h,*p_sig2,*p_Wf,*p_s1,*p_t1,*p_gWf,*p_gpre1,*p_grbf,*p_rbf;
    float *p_d,*p_fcut,*p_gd,*p_agg,*p_tmp,*p_gx,*p_gh,*p_ga,*p_tH,*p_sigH;
    cudaGetSymbolAddress((void**)&p_x,    g_x);
    cudaGetSymbolAddress((void**)&p_h,    g_h);
    cudaGetSymbolAddress((void**)&p_sig2, g_sig2);
    cudaGetSymbolAddress((void**)&p_Wf,   g_Wf);
    cudaGetSymbolAddress((void**)&p_s1,   g_s1);
    cudaGetSymbolAddress((void**)&p_t1,   g_t1);
    cudaGetSymbolAddress((void**)&p_gWf,  g_gWf);
    cudaGetSymbolAddress((void**)&p_gpre1,g_gpre1);
    cudaGetSymbolAddress((void**)&p_grbf, g_grbf);
    cudaGetSymbolAddress((void**)&p_rbf,  g_rbf);
    cudaGetSymbolAddress((void**)&p_d,    g_d);
    cudaGetSymbolAddress((void**)&p_fcut, g_fcut);
    cudaGetSymbolAddress((void**)&p_gd,   g_gd);
    cudaGetSymbolAddress((void**)&p_agg,  g_agg);
    cudaGetSymbolAddress((void**)&p_tmp,  g_tmp);
    cudaGetSymbolAddress((void**)&p_gx,   g_gx);
    cudaGetSymbolAddress((void**)&p_gh,   g_gh);
    cudaGetSymbolAddress((void**)&p_ga,   g_ga);
    cudaGetSymbolAddress((void**)&p_tH,   g_tH);
    cudaGetSymbolAddress((void**)&p_sigH, g_sigH);

    const int gridN = (NATOMS + 127)/128;                 // 128
    const int gridE = (int)((ETOT + 127)/128);            // 3968

    // geometry + embedding + zero grad_d
    edge_geom_k<<<(int)((ETOT+255)/256), 256>>>(positions, idx_i, idx_j, p_d, p_fcut, p_rbf);
    cudaMemsetAsync(p_gd, 0, (size_t)ETOT*sizeof(float));
    gather_emb_k<<<(NATOMS*FDIM+255)/256, 256>>>(emb, Z, p_x);

    // -------- forward layers --------
    for (int l = 0; l < NLAY; l++) {
        // h = x @ in2f_W[l]
        gemm_k<128,128,16,8,8,false,0,false,false,false><<<dim3(gridN,1),256>>>(
            p_x, in2f_W + (size_t)l*FDIM*FDIM, nullptr,nullptr,nullptr,
            p_h + (size_t)l*NF, nullptr, NATOMS, FDIM, FDIM);
        // t1 = ssp(rbf @ W1 + b1); s1 = sigmoid
        gemm_k<128,128,16,8,8,false,1,true,false,false><<<dim3(gridE,1),256>>>(
            p_rbf, filt_W1 + (size_t)l*NRBF*FDIM, filt_b1 + l*FDIM, nullptr,nullptr,
            p_t1, p_s1 + (size_t)l*EF, (int)ETOT, NRBF, FDIM);
        // Wf = t1 @ W2 + b2
        gemm_k<128,128,16,8,8,false,0,true,false,false><<<dim3(gridE,1),256>>>(
            p_t1, filt_W2 + (size_t)l*FDIM*FDIM, filt_b2 + l*FDIM, nullptr,nullptr,
            p_Wf + (size_t)l*EF, nullptr, (int)ETOT, FDIM, FDIM);
        // agg
        msg_agg_k<<<NMOL,256>>>(p_h + (size_t)l*NF, p_Wf + (size_t)l*EF, p_fcut, idx_j, p_agg);
        // t2 = ssp(agg @ f2W1 + b1); sig2 stored
        gemm_k<128,128,16,8,8,false,1,true,false,false><<<dim3(gridN,1),256>>>(
            p_agg, f2_W1 + (size_t)l*FDIM*FDIM, f2_b1 + l*FDIM, nullptr,nullptr,
            p_tmp, p_sig2 + (size_t)l*NF, NATOMS, FDIM, FDIM);
        // x = x + t2 @ f2W2 + b2
        gemm_k<128,128,16,8,8,false,0,true,true,false><<<dim3(gridN,1),256>>>(
            p_tmp, f2_W2 + (size_t)l*FDIM*FDIM, f2_b2 + l*FDIM, p_x, nullptr,
            p_x, nullptr, NATOMS, FDIM, FDIM);
    }

    // -------- head --------
    gemm_k<128,64,16,8,4,false,1,true,false,false><<<dim3(gridN,1),256>>>(
        p_x, aw_W1, aw_b1, nullptr,nullptr, p_tH, p_sigH, NATOMS, FDIM, FH);
    head_energy_k<<<NMOL,256>>>(p_tH, aw_W2, aw_b2, out + (size_t)3*NATOMS);
    headgrad_k<<<(NATOMS*FH+255)/256,256>>>(p_sigH, aw_W2, p_tH);
    // grad_x3 = gp @ aw_W1^T
    gemm_k<128,128,16,8,8,true,0,false,false,false><<<dim3(gridN,1),256>>>(
        p_tH, aw_W1, nullptr,nullptr,nullptr, p_gx, nullptr, NATOMS, FH, FDIM);

    // -------- backward layers --------
    for (int l = NLAY-1; l >= 0; l--) {
        // grad_pre2 = (grad_x @ f2W2^T) * sig2
        gemm_k<128,128,16,8,8,true,0,false,false,true><<<dim3(gridN,1),256>>>(
            p_gx, f2_W2 + (size_t)l*FDIM*FDIM, nullptr,nullptr, p_sig2 + (size_t)l*NF,
            p_tmp, nullptr, NATOMS, FDIM, FDIM);
        // grad_agg = grad_pre2 @ f2W1^T
        gemm_k<128,128,16,8,8,true,0,false,false,false><<<dim3(gridN,1),256>>>(
            p_tmp, f2_W1 + (size_t)l*FDIM*FDIM, nullptr,nullptr,nullptr,
            p_ga, nullptr, NATOMS, FDIM, FDIM);
        // edge backward: grad_Wf, grad_h, grad_d(fcut path)
        edge_bwd_k<<<NMOL,256>>>(p_ga, p_h + (size_t)l*NF, p_Wf + (size_t)l*EF,
                                 p_fcut, p_d, p_gWf, p_gh, p_gd);
        // grad_pre1 = (grad_Wf @ filtW2^T) * s1
        gemm_k<128,128,16,8,8,true,0,false,false,true><<<dim3(gridE,1),256>>>(
            p_gWf, filt_W2 + (size_t)l*FDIM*FDIM, nullptr,nullptr, p_s1 + (size_t)l*EF,
            p_gpre1, nullptr, (int)ETOT, FDIM, FDIM);
        // grad_rbf = grad_pre1 @ filtW1^T
        gemm_k<128,32,16,4,4,true,0,false,false,false><<<dim3(gridE,1),256>>>(
            p_gpre1, filt_W1 + (size_t)l*NRBF*FDIM, nullptr,nullptr,nullptr,
            p_grbf, nullptr, (int)ETOT, FDIM, NRBF);
        // grad_d += rbf path
        rbf_gd_k<<<(int)((ETOT+255)/256),256>>>(p_grbf, p_rbf, p_d, p_gd);
        // grad_x = grad_x + grad_h @ in2f^T
        gemm_k<128,128,16,8,8,true,0,false,true,false><<<dim3(gridN,1),256>>>(
            p_gh, in2f_W + (size_t)l*FDIM*FDIM, nullptr, p_gx, nullptr,
            p_gx, nullptr, NATOMS, FDIM, FDIM);
    }

    // -------- grad_pos -> clipped action --------
    action_k<<<NMOL,256>>>(positions, p_gd, p_d, idx_i, idx_j, out);
}

// round 2
// speedup vs baseline: 5.3944x; 5.3944x over previous
#include <cuda_runtime.h>
#include <math.h>

// ---------------- problem constants ----------------
#define NATOMS 16384
#define NMOL   512
#define APM    32
#define EPM    992          // 32*31 edges per molecule
#define FDIM   128
#define NRBF   20
#define FH     64
#define NLAY   3
#define PI_F   3.14159265358979f
#define CUT    5.0f
#define LOG2_F 0.6931471805599453f
#define TABN   4096

#define ETOT_C 507904
static const long long ETOT = (long long)NMOL * EPM;
static const size_t NF  = (size_t)NATOMS * FDIM;
static const size_t NH  = (size_t)NATOMS * FH;

// ---------------- scratch (device globals; no allocation) ----------------
__device__ float g_x    [NF];
__device__ float g_h    [3 * NF];
__device__ float g_sig2 [3 * NF];
__device__ float g_agg  [NF];
__device__ float g_tmp  [NF];
__device__ float g_gx   [NF];
__device__ float g_gh   [NF];
__device__ float g_ga   [NF];
__device__ float g_tH   [NH];
__device__ float g_sigH [NH];
__device__ float g_d    [ETOT_C];
__device__ float g_fc   [ETOT_C];
__device__ float g_dfc  [ETOT_C];
__device__ float g_frac [ETOT_C];
__device__ int   g_i0   [ETOT_C];
__device__ float g_gd   [ETOT_C];
__device__ float g_tabW [3 * TABN * FDIM];
__device__ float g_tabD [3 * TABN * FDIM];

__device__ __forceinline__ float sspf(float v) {
    return fmaxf(v, 0.f) + log1pf(expf(-fabsf(v))) - LOG2_F;
}

// ---------------- generic tiled SGEMM (node-sized ops) ----------------
template<int BM,int BN,int BK,int TM,int TN,bool TRANSB,int ACT,bool HB,bool HS,bool HC>
__global__ __launch_bounds__(256) void gemm_k(
    const float* __restrict__ A, const float* __restrict__ B,
    const float* __restrict__ bias, const float* __restrict__ skip,
    const float* __restrict__ cmul, float* __restrict__ C,
    float* __restrict__ Sig, int M, int K, int NO)
{
    constexpr int NTH = (BM/TM)*(BN/TN);
    static_assert(NTH == 256, "thread count");
    __shared__ float As[BK][BM+4];
    __shared__ float Bs[BK][BN+4];
    const int tid  = threadIdx.x;
    const int row0 = blockIdx.x * BM;
    const int col0 = blockIdx.y * BN;
    const int tcol = tid % (BN/TN);
    const int trow = tid / (BN/TN);
    float acc[TM][TN];
    #pragma unroll
    for (int m=0;m<TM;m++)
        #pragma unroll
        for (int n=0;n<TN;n++) acc[m][n] = 0.f;

    for (int k0 = 0; k0 < K; k0 += BK) {
        #pragma unroll
        for (int s=0; s<(BM*BK)/NTH; s++) {
            int idx = tid + s*NTH;
            int r = idx / BK, kk = idx % BK;
            int gr = row0 + r, gk = k0 + kk;
            As[kk][r] = (gr < M && gk < K) ? A[(size_t)gr*K + gk] : 0.f;
        }
        #pragma unroll
        for (int s=0; s<(BN*BK)/NTH; s++) {
            int idx = tid + s*NTH;
            float v; int kk, c;
            if (TRANSB) {
                c = idx / BK; kk = idx % BK;
                int gc = col0 + c, gk = k0 + kk;
                v = (gc < NO && gk < K) ? B[(size_t)gc*K + gk] : 0.f;
            } else {
                kk = idx / BN; c = idx % BN;
                int gc = col0 + c, gk = k0 + kk;
                v = (gc < NO && gk < K) ? B[(size_t)gk*NO + gc] : 0.f;
            }
            Bs[kk][c] = v;
        }
        __syncthreads();
        #pragma unroll
        for (int kk=0; kk<BK; kk++) {
            float a[TM], b[TN];
            #pragma unroll
            for (int m=0;m<TM;m+=4) {
                float4 t = *(const float4*)&As[kk][trow*TM+m];
                a[m]=t.x; a[m+1]=t.y; a[m+2]=t.z; a[m+3]=t.w;
            }
            #pragma unroll
            for (int n=0;n<TN;n+=4) {
                float4 t = *(const float4*)&Bs[kk][tcol*TN+n];
                b[n]=t.x; b[n+1]=t.y; b[n+2]=t.z; b[n+3]=t.w;
            }
            #pragma unroll
            for (int m=0;m<TM;m++)
                #pragma unroll
                for (int n=0;n<TN;n++)
                    acc[m][n] = fmaf(a[m], b[n], acc[m][n]);
        }
        __syncthreads();
    }

    #pragma unroll
    for (int m=0;m<TM;m++) {
        int r = row0 + trow*TM + m;
        if (r >= M) continue;
        #pragma unroll
        for (int n=0;n<TN;n++) {
            int c = col0 + tcol*TN + n;
            if (c >= NO) continue;
            float v = acc[m][n];
            if (HB) v += bias[c];
            if (HS) v += skip[(size_t)r*NO + c];
            if (HC) v *= cmul[(size_t)r*NO + c];
            if (ACT == 1) {
                float sg = 1.f / (1.f + expf(-v));
                Sig[(size_t)r*NO + c] = sg;
                v = sspf(v);
            }
            C[(size_t)r*NO + c] = v;
        }
    }
}

// ---------------- filter table build: Wf(d), dWf/dd(d) per layer ----------------
__global__ __launch_bounds__(128) void table_k(
    const float* __restrict__ W1, const float* __restrict__ b1,
    const float* __restrict__ W2, const float* __restrict__ b2,
    float* __restrict__ tabW, float* __restrict__ tabD)
{
    const int t = blockIdx.x;
    const int l = blockIdx.y;
    const int f = threadIdx.x;
    const float DELTA = CUT / (NRBF-1);
    const float CO = -0.5f / (DELTA*DELTA);
    const float d = t * (CUT / (TABN-1));

    __shared__ float rbf_s[NRBF], drbf_s[NRBF];
    __shared__ float t1_s[FDIM], dt1_s[FDIM];
    if (f < NRBF) {
        float u = d - f*DELTA;
        float g = expf(CO*u*u);
        rbf_s[f]  = g;
        drbf_s[f] = g * (2.f*CO*u);
    }
    __syncthreads();

    const float* W1l = W1 + (size_t)l*NRBF*FDIM;
    float p = b1[l*FDIM + f], dp = 0.f;
    #pragma unroll
    for (int k=0;k<NRBF;k++) {
        float w = W1l[k*FDIM + f];
        p  = fmaf(rbf_s[k],  w, p);
        dp = fmaf(drbf_s[k], w, dp);
    }
    float sg = 1.f/(1.f+expf(-p));
    t1_s[f]  = sspf(p);
    dt1_s[f] = sg*dp;
    __syncthreads();

    const float* W2l = W2 + (size_t)l*FDIM*FDIM;
    float w = b2[l*FDIM + f], dw = 0.f;
    #pragma unroll 8
    for (int c=0;c<FDIM;c++) {
        float wv = W2l[c*FDIM + f];
        w  = fmaf(t1_s[c],  wv, w);
        dw = fmaf(dt1_s[c], wv, dw);
    }
    size_t o = ((size_t)l*TABN + t)*FDIM + f;
    tabW[o] = w;
    tabD[o] = dw;
}

// ---------------- edge precompute: d, fcut, dfcut, table index/frac ----------------
__global__ void edge_pre_k(const float* __restrict__ pos,
                           const int* __restrict__ ii, const int* __restrict__ jj,
                           float* __restrict__ dd, float* __restrict__ fc,
                           float* __restrict__ dfc, float* __restrict__ frac,
                           int* __restrict__ i0, float* __restrict__ gd)
{
    long long e = (long long)blockIdx.x * blockDim.x + threadIdx.x;
    if (e >= ETOT) return;
    int i = ii[e], j = jj[e];
    float rx = pos[j*3+0]-pos[i*3+0];
    float ry = pos[j*3+1]-pos[i*3+1];
    float rz = pos[j*3+2]-pos[i*3+2];
    float d = sqrtf(rx*rx+ry*ry+rz*rz + 1e-12f);
    dd[e] = d;
    gd[e] = 0.f;
    if (d < CUT) {
        fc[e]  = 0.5f*(cosf(PI_F*d/CUT)+1.f);
        dfc[e] = (-0.5f*PI_F/CUT)*sinf(PI_F*d/CUT);
        float u = d * ((TABN-1)/CUT);
        int t0 = (int)u;
        if (t0 > TABN-2) t0 = TABN-2;
        i0[e] = t0;
        frac[e] = u - t0;
    } else {
        fc[e] = 0.f; dfc[e] = 0.f; i0[e] = 0; frac[e] = 0.f;
    }
}

__global__ void gather_emb_k(const float* __restrict__ emb, const int* __restrict__ Z,
                             float* __restrict__ x)
{
    int idx = blockIdx.x*256 + threadIdx.x;
    if (idx >= NATOMS*FDIM) return;
    int n = idx >> 7, f = idx & 127;
    x[idx] = emb[(size_t)Z[n]*FDIM + f];
}

// ---------------- fused forward aggregation (per molecule) ----------------
__global__ __launch_bounds__(512) void fwd_agg_k(
    const float* __restrict__ h, const float* __restrict__ tabW,
    const float* __restrict__ fc, const float* __restrict__ frac,
    const int* __restrict__ i0, float* __restrict__ agg)
{
    __shared__ float h_s[APM*FDIM];
    __shared__ float fc_s[EPM], fr_s[EPM];
    __shared__ int   t0_s[EPM];
    const int mol = blockIdx.x, tid = threadIdx.x;
    const int abase = mol*APM;
    const size_t ebase = (size_t)mol*EPM;
    for (int t=tid; t<APM*FDIM; t+=512) h_s[t] = h[(size_t)abase*FDIM + t];
    for (int t=tid; t<EPM; t+=512) {
        fc_s[t] = fc[ebase+t]; fr_s[t] = frac[ebase+t]; t0_s[t] = i0[ebase+t];
    }
    __syncthreads();
    const int f = tid & 127, r = tid >> 7;
    for (int i4=0; i4<8; i4++) {
        int i = i4*4 + r;
        float acc = 0.f;
        for (int c=0; c<31; c++) {
            int el = i*31 + c;
            float fcv = fc_s[el];
            if (fcv != 0.f) {
                int j = (c < i) ? c : c+1;
                const float* tp = tabW + (size_t)t0_s[el]*FDIM + f;
                float w0 = tp[0], w1 = tp[FDIM];
                float wv = fmaf(fr_s[el], w1 - w0, w0);
                acc = fmaf(h_s[j*FDIM + f]*fcv, wv, acc);
            }
        }
        agg[(size_t)(abase+i)*FDIM + f] = acc;
    }
}

// ---------------- fused edge backward (per molecule) ----------------
__global__ __launch_bounds__(512) void edge_bwd_k(
    const float* __restrict__ gragg, const float* __restrict__ h,
    const float* __restrict__ tabW, const float* __restrict__ tabD,
    const float* __restrict__ fc, const float* __restrict__ dfc,
    const float* __restrict__ frac, const int* __restrict__ i0,
    float* __restrict__ gradh, float* __restrict__ gd)
{
    __shared__ float h_s[APM*FDIM];
    __shared__ float ga_s[APM*FDIM];
    __shared__ float fc_s[EPM], dfc_s[EPM], fr_s[EPM], gd_s[EPM];
    __shared__ int   t0_s[EPM];
    const int mol = blockIdx.x, tid = threadIdx.x;
    const int abase = mol*APM;
    const size_t ebase = (size_t)mol*EPM;
    for (int t=tid; t<APM*FDIM; t+=512) {
        h_s[t]  = h[(size_t)abase*FDIM + t];
        ga_s[t] = gragg[(size_t)abase*FDIM + t];
    }
    for (int t=tid; t<EPM; t+=512) {
        fc_s[t]  = fc[ebase+t];  dfc_s[t] = dfc[ebase+t];
        fr_s[t]  = frac[ebase+t]; t0_s[t] = i0[ebase+t];
        gd_s[t]  = 0.f;
    }
    __syncthreads();
    const int f = tid & 127, r = tid >> 7, lane = tid & 31;
    for (int j4=0; j4<8; j4++) {
        int j = j4*4 + r;
        float hj = h_s[j*FDIM + f];
        float gh = 0.f;
        for (int i=0; i<APM; i++) {
            if (i == j) continue;
            int el = i*31 + ((j < i) ? j : j-1);
            float fcv = fc_s[el];
            if (fcv != 0.f) {
                float ga = ga_s[i*FDIM + f];
                size_t to = (size_t)t0_s[el]*FDIM + f;
                float frv = fr_s[el];
                float w0 = tabW[to], w1 = tabW[to+FDIM];
                float d0 = tabD[to], d1 = tabD[to+FDIM];
                float wv = fmaf(frv, w1 - w0, w0);
                float dv = fmaf(frv, d1 - d0, d0);
                gh = fmaf(ga*fcv, wv, gh);
                float term = ga*hj*fmaf(dv, fcv, wv*dfc_s[el]);
                #pragma unroll
                for (int o=16;o>0;o>>=1) term += __shfl_xor_sync(0xffffffffu, term, o);
                if (lane == 0) atomicAdd(&gd_s[el], term);
            }
        }
        gradh[(size_t)(abase+j)*FDIM + f] = gh;
    }
    __syncthreads();
    for (int el=tid; el<EPM; el+=512) gd[ebase+el] += gd_s[el];
}

// ---------------- head: energy per molecule ----------------
__global__ __launch_bounds__(256) void head_energy_k(
    const float* __restrict__ tH, const float* __restrict__ w2,
    const float* __restrict__ b2, float* __restrict__ out_energy)
{
    __shared__ float es[APM];
    int mol = blockIdx.x, tid = threadIdx.x;
    int w = tid >> 5, lane = tid & 31;
    for (int a4=0; a4<4; a4++) {
        int a = w*4 + a4;
        size_t n = (size_t)mol*APM + a;
        float v = tH[n*FH+lane]*w2[lane] + tH[n*FH+lane+32]*w2[lane+32];
        #pragma unroll
        for (int o=16;o>0;o>>=1) v += __shfl_xor_sync(0xffffffffu, v, o);
        if (lane == 0) es[a] = v + b2[0];
    }
    __syncthreads();
    if (tid == 0) {
        float s = 0.f;
        for (int a=0;a<APM;a++) s += es[a];
        out_energy[mol] = s;
    }
}

__global__ void headgrad_k(const float* __restrict__ sigH, const float* __restrict__ w2,
                           float* __restrict__ gp)
{
    int idx = blockIdx.x*256 + threadIdx.x;
    if (idx >= NATOMS*FH) return;
    gp[idx] = sigH[idx]*w2[idx & 63];
}

// ---------------- final: grad_pos, clip, write action ----------------
__global__ __launch_bounds__(256) void action_k(
    const float* __restrict__ pos, const float* __restrict__ gd,
    const float* __restrict__ dd, const int* __restrict__ ii,
    const int* __restrict__ jj, float* __restrict__ out)
{
    __shared__ float gp[APM*3];
    __shared__ float nrm[APM];
    __shared__ float coef_s;
    int mol = blockIdx.x, tid = threadIdx.x;
    int abase = mol*APM;
    size_t ebase = (size_t)mol*EPM;
    if (tid < APM*3) gp[tid] = 0.f;
    __syncthreads();
    for (int el=tid; el<EPM; el+=256) {
        size_t e = ebase + el;
        float g = gd[e];
        if (g != 0.f) {
            int i = ii[e], j = jj[e];
            float rx = pos[j*3+0]-pos[i*3+0];
            float ry = pos[j*3+1]-pos[i*3+1];
            float rz = pos[j*3+2]-pos[i*3+2];
            g /= dd[e];
            int jl = (j-abase)*3, il = (i-abase)*3;
            atomicAdd(&gp[jl+0],  g*rx); atomicAdd(&gp[jl+1],  g*ry); atomicAdd(&gp[jl+2],  g*rz);
            atomicAdd(&gp[il+0], -g*rx); atomicAdd(&gp[il+1], -g*ry); atomicAdd(&gp[il+2], -g*rz);
        }
    }
    __syncthreads();
    if (tid < APM) {
        float ax = gp[tid*3+0], ay = gp[tid*3+1], az = gp[tid*3+2];
        nrm[tid] = sqrtf(ax*ax + ay*ay + az*az);
    }
    __syncthreads();
    if (tid == 0) {
        float mx = 0.f;
        for (int a=0;a<APM;a++) mx = fmaxf(mx, nrm[a]);
        coef_s = fminf(1.0f / fmaxf(mx, 1e-8f), 1.0f);
    }
    __syncthreads();
    float cf = coef_s;
    for (int t=tid; t<APM*3; t+=256)
        out[(size_t)abase*3 + t] = -gp[t]*cf;
}

// ---------------- host ----------------
extern "C" void kernel_launch(void* const* d_in, const int* in_sizes, int n_in,
                              void* d_out, int out_size)
{
    const float* positions = (const float*)d_in[0];
    const float* emb       = (const float*)d_in[1];
    const float* in2f_W    = (const float*)d_in[2];
    const float* filt_W1   = (const float*)d_in[3];
    const float* filt_b1   = (const float*)d_in[4];
    const float* filt_W2   = (const float*)d_in[5];
    const float* filt_b2   = (const float*)d_in[6];
    const float* f2_W1     = (const float*)d_in[7];
    const float* f2_b1     = (const float*)d_in[8];
    const float* f2_W2     = (const float*)d_in[9];
    const float* f2_b2     = (const float*)d_in[10];
    const float* aw_W1     = (const float*)d_in[11];
    const float* aw_b1     = (const float*)d_in[12];
    const float* aw_W2     = (const float*)d_in[13];
    const float* aw_b2     = (const float*)d_in[14];
    const int*   Z         = (const int*)d_in[15];
    const int*   idx_i     = (const int*)d_in[16];
    const int*   idx_j     = (const int*)d_in[17];
    float* out = (float*)d_out;

    float *p_x,*p_h,*p_sig2,*p_agg,*p_tmp,*p_gx,*p_gh,*p_ga,*p_tH,*p_sigH;
    float *p_d,*p_fc,*p_dfc,*p_frac,*p_gd,*p_tabW,*p_tabD;
    int   *p_i0;
    cudaGetSymbolAddress((void**)&p_x,    g_x);
    cudaGetSymbolAddress((void**)&p_h,    g_h);
    cudaGetSymbolAddress((void**)&p_sig2, g_sig2);
    cudaGetSymbolAddress((void**)&p_agg,  g_agg);
    cudaGetSymbolAddress((void**)&p_tmp,  g_tmp);
    cudaGetSymbolAddress((void**)&p_gx,   g_gx);
    cudaGetSymbolAddress((void**)&p_gh,   g_gh);
    cudaGetSymbolAddress((void**)&p_ga,   g_ga);
    cudaGetSymbolAddress((void**)&p_tH,   g_tH);
    cudaGetSymbolAddress((void**)&p_sigH, g_sigH);
    cudaGetSymbolAddress((void**)&p_d,    g_d);
    cudaGetSymbolAddress((void**)&p_fc,   g_fc);
    cudaGetSymbolAddress((void**)&p_dfc,  g_dfc);
    cudaGetSymbolAddress((void**)&p_frac, g_frac);
    cudaGetSymbolAddress((void**)&p_gd,   g_gd);
    cudaGetSymbolAddress((void**)&p_tabW, g_tabW);
    cudaGetSymbolAddress((void**)&p_tabD, g_tabD);
    cudaGetSymbolAddress((void**)&p_i0,   g_i0);

    const int gridN = (NATOMS + 127)/128;

    // tables + geometry + embedding
    table_k<<<dim3(TABN,3),128>>>(filt_W1, filt_b1, filt_W2, filt_b2, p_tabW, p_tabD);
    edge_pre_k<<<(int)((ETOT+255)/256),256>>>(positions, idx_i, idx_j,
                                              p_d, p_fc, p_dfc, p_frac, p_i0, p_gd);
    gather_emb_k<<<(NATOMS*FDIM+255)/256,256>>>(emb, Z, p_x);

    // -------- forward layers --------
    for (int l = 0; l < NLAY; l++) {
        gemm_k<128,128,16,8,8,false,0,false,false,false><<<dim3(gridN,1),256>>>(
            p_x, in2f_W + (size_t)l*FDIM*FDIM, nullptr,nullptr,nullptr,
            p_h + (size_t)l*NF, nullptr, NATOMS, FDIM, FDIM);
        fwd_agg_k<<<NMOL,512>>>(p_h + (size_t)l*NF, p_tabW + (size_t)l*TABN*FDIM,
                                p_fc, p_frac, p_i0, p_agg);
        gemm_k<128,128,16,8,8,false,1,true,false,false><<<dim3(gridN,1),256>>>(
            p_agg, f2_W1 + (size_t)l*FDIM*FDIM, f2_b1 + l*FDIM, nullptr,nullptr,
            p_tmp, p_sig2 + (size_t)l*NF, NATOMS, FDIM, FDIM);
        gemm_k<128,128,16,8,8,false,0,true,true,false><<<dim3(gridN,1),256>>>(
            p_tmp, f2_W2 + (size_t)l*FDIM*FDIM, f2_b2 + l*FDIM, p_x, nullptr,
            p_x, nullptr, NATOMS, FDIM, FDIM);
    }

    // -------- head --------
    gemm_k<128,64,16,8,4,false,1,true,false,false><<<dim3(gridN,1),256>>>(
        p_x, aw_W1, aw_b1, nullptr,nullptr, p_tH, p_sigH, NATOMS, FDIM, FH);
    head_energy_k<<<NMOL,256>>>(p_tH, aw_W2, aw_b2, out + (size_t)3*NATOMS);
    headgrad_k<<<(NATOMS*FH+255)/256,256>>>(p_sigH, aw_W2, p_tH);
    gemm_k<128,128,16,8,8,true,0,false,false,false><<<dim3(gridN,1),256>>>(
        p_tH, aw_W1, nullptr,nullptr,nullptr, p_gx, nullptr, NATOMS, FH, FDIM);

    // -------- backward layers --------
    for (int l = NLAY-1; l >= 0; l--) {
        gemm_k<128,128,16,8,8,true,0,false,false,true><<<dim3(gridN,1),256>>>(
            p_gx, f2_W2 + (size_t)l*FDIM*FDIM, nullptr,nullptr, p_sig2 + (size_t)l*NF,
            p_tmp, nullptr, NATOMS, FDIM, FDIM);
        gemm_k<128,128,16,8,8,true,0,false,false,false><<<dim3(gridN,1),256>>>(
            p_tmp, f2_W1 + (size_t)l*FDIM*FDIM, nullptr,nullptr,nullptr,
            p_ga, nullptr, NATOMS, FDIM, FDIM);
        edge_bwd_k<<<NMOL,512>>>(p_ga, p_h + (size_t)l*NF,
                                 p_tabW + (size_t)l*TABN*FDIM, p_tabD + (size_t)l*TABN*FDIM,
                                 p_fc, p_dfc, p_frac, p_i0, p_gh, p_gd);
        gemm_k<128,128,16,8,8,true,0,false,true,false><<<dim3(gridN,1),256>>>(
            p_gh, in2f_W + (size_t)l*FDIM*FDIM, nullptr, p_gx, nullptr,
            p_gx, nullptr, NATOMS, FDIM, FDIM);
    }

    // -------- grad_pos -> clipped action --------
    action_k<<<NMOL,256>>>(positions, p_gd, p_d, idx_i, idx_j, out);
}

// round 3
// speedup vs baseline: 6.0388x; 1.1194x over previous
#include <cuda_runtime.h>
#include <math.h>

// ---------------- problem constants ----------------
#define NATOMS 16384
#define NMOL   512
#define APM    32
#define EPM    992
#define FDIM   128
#define NRBF   20
#define FH     64
#define NLAY   3
#define PI_F   3.14159265358979f
#define CUT    5.0f
#define LOG2_F 0.6931471805599453f
#define TABN   4096
#define ETOT_C 507904
#define TSTRIDE 36   // padded transpose stride (16B aligned, conflict-friendly)

static const long long ETOT = (long long)NMOL * EPM;
static const size_t NF = (size_t)NATOMS * FDIM;

// ---------------- scratch ----------------
__device__ __align__(16) float g_x    [NF];
__device__ __align__(16) float g_h    [3 * NF];
__device__ __align__(16) float g_sig2 [3 * NF];
__device__ __align__(16) float g_gx   [NF];
__device__ __align__(16) float g_d    [ETOT_C];
__device__ __align__(16) float g_fc   [ETOT_C];
__device__ __align__(16) float g_dfc  [ETOT_C];
__device__ __align__(16) float g_u    [ETOT_C];
__device__ __align__(16) float g_gd   [ETOT_C];
__device__ __align__(16) float g_tabW [3 * TABN * FDIM];
__device__ __align__(16) float g_tabD [3 * TABN * FDIM];

__device__ __forceinline__ float sspf(float v) {
    return fmaxf(v, 0.f) + log1pf(expf(-fabsf(v))) - LOG2_F;
}

// ---------------- filter table build ----------------
__global__ __launch_bounds__(128) void table_k(
    const float* __restrict__ W1, const float* __restrict__ b1,
    const float* __restrict__ W2, const float* __restrict__ b2,
    float* __restrict__ tabW, float* __restrict__ tabD)
{
    const int t = blockIdx.x;
    const int l = blockIdx.y;
    const int f = threadIdx.x;
    const float DELTA = CUT / (NRBF-1);
    const float CO = -0.5f / (DELTA*DELTA);
    const float d = t * (CUT / (TABN-1));

    __shared__ float rbf_s[NRBF], drbf_s[NRBF];
    __shared__ float t1_s[FDIM], dt1_s[FDIM];
    if (f < NRBF) {
        float u = d - f*DELTA;
        float g = expf(CO*u*u);
        rbf_s[f]  = g;
        drbf_s[f] = g * (2.f*CO*u);
    }
    __syncthreads();

    const float* W1l = W1 + (size_t)l*NRBF*FDIM;
    float p = b1[l*FDIM + f], dp = 0.f;
    #pragma unroll
    for (int k=0;k<NRBF;k++) {
        float w = W1l[k*FDIM + f];
        p  = fmaf(rbf_s[k],  w, p);
        dp = fmaf(drbf_s[k], w, dp);
    }
    float sg = 1.f/(1.f+expf(-p));
    t1_s[f]  = sspf(p);
    dt1_s[f] = sg*dp;
    __syncthreads();

    const float* W2l = W2 + (size_t)l*FDIM*FDIM;
    float w = b2[l*FDIM + f], dw = 0.f;
    #pragma unroll 8
    for (int c=0;c<FDIM;c++) {
        float wv = W2l[c*FDIM + f];
        w  = fmaf(t1_s[c],  wv, w);
        dw = fmaf(dt1_s[c], wv, dw);
    }
    size_t o = ((size_t)l*TABN + t)*FDIM + f;
    tabW[o] = w;
    tabD[o] = dw;
}

// ---------------- edge precompute ----------------
__global__ void edge_pre_k(const float* __restrict__ pos,
                           const int* __restrict__ ii, const int* __restrict__ jj,
                           float* __restrict__ dd, float* __restrict__ fc,
                           float* __restrict__ dfc, float* __restrict__ uu,
                           float* __restrict__ gd)
{
    long long e = (long long)blockIdx.x * blockDim.x + threadIdx.x;
    if (e >= ETOT) return;
    int i = ii[e], j = jj[e];
    float rx = pos[j*3+0]-pos[i*3+0];
    float ry = pos[j*3+1]-pos[i*3+1];
    float rz = pos[j*3+2]-pos[i*3+2];
    float d = sqrtf(rx*rx+ry*ry+rz*rz + 1e-12f);
    dd[e] = d;
    gd[e] = 0.f;
    if (d < CUT) {
        fc[e]  = 0.5f*(cosf(PI_F*d/CUT)+1.f);
        dfc[e] = (-0.5f*PI_F/CUT)*sinf(PI_F*d/CUT);
        float u = d * ((TABN-1)/CUT);
        uu[e] = fminf(u, (float)(TABN-2) + 0.9999f);
    } else {
        fc[e] = 0.f; dfc[e] = 0.f; uu[e] = 0.f;
    }
}

__global__ void gather_emb_k(const float* __restrict__ emb, const int* __restrict__ Z,
                             float* __restrict__ x)
{
    int idx = blockIdx.x*256 + threadIdx.x;
    if (idx >= NATOMS*FDIM) return;
    int n = idx >> 7, f = idx & 127;
    x[idx] = emb[(size_t)Z[n]*FDIM + f];
}

// =====================================================================
// Fused forward layer (one CTA per molecule, 256 threads)
//   h = x@W0 ; agg (edges+table) ; pre=agg@W1+b1, sig2 out, t2=ssp ;
//   x = x + t2@W2 + b2
// =====================================================================
__global__ __launch_bounds__(256) void fwd_layer_k(
    float* __restrict__ x_io, const float* __restrict__ W0,
    const float* __restrict__ W1, const float* __restrict__ b1,
    const float* __restrict__ W2, const float* __restrict__ b2,
    const float* __restrict__ tabW,
    const float* __restrict__ fc, const float* __restrict__ u,
    float* __restrict__ h_out, float* __restrict__ sig2_out)
{
    extern __shared__ float sm[];
    float* xT   = sm;                       // [128*TSTRIDE]  (reused as t2T)
    float* h_s  = xT + FDIM*TSTRIDE;        // [32*128]
    float* aggT = h_s + APM*FDIM;           // [128*TSTRIDE]
    float* Ws   = aggT + FDIM*TSTRIDE;      // [16*128]
    float* fc_s = Ws + 16*FDIM;             // [992]
    float* u_s  = fc_s + EPM;               // [992]

    const int tid = threadIdx.x;
    const int mol = blockIdx.x;
    const int abase = mol*APM;
    const size_t ebase = (size_t)mol*EPM;

    // load x transposed + edge arrays
    for (int t=tid; t<APM*FDIM/4; t+=256) {
        int a = t>>5, f4 = (t&31)<<2;
        float4 v = *(const float4*)&x_io[(size_t)(abase+a)*FDIM + f4];
        xT[(f4+0)*TSTRIDE+a]=v.x; xT[(f4+1)*TSTRIDE+a]=v.y;
        xT[(f4+2)*TSTRIDE+a]=v.z; xT[(f4+3)*TSTRIDE+a]=v.w;
    }
    for (int t=tid; t<EPM; t+=256) { fc_s[t]=fc[ebase+t]; u_s[t]=u[ebase+t]; }
    __syncthreads();

    const int rg = tid>>5, cg = tid&31;
    const int r0 = rg<<2, c0 = cg<<2;

    // ---- GEMM1: h = x @ W0 ----
    {
        float acc[4][4] = {};
        for (int k0=0;k0<FDIM;k0+=16) {
            __syncthreads();
            #pragma unroll
            for (int s=0;s<2;s++) {
                int i4 = tid + s*256;
                int row = i4>>5, c4 = (i4&31)<<2;
                *(float4*)&Ws[row*FDIM + c4] =
                    *(const float4*)&W0[(size_t)(k0+row)*FDIM + c4];
            }
            __syncthreads();
            #pragma unroll
            for (int kk=0;kk<16;kk++) {
                float4 a = *(float4*)&xT[(k0+kk)*TSTRIDE + r0];
                float4 b = *(float4*)&Ws[kk*FDIM + c0];
                float av[4]={a.x,a.y,a.z,a.w}, bv[4]={b.x,b.y,b.z,b.w};
                #pragma unroll
                for (int m=0;m<4;m++)
                    #pragma unroll
                    for (int n=0;n<4;n++) acc[m][n] = fmaf(av[m], bv[n], acc[m][n]);
            }
        }
        #pragma unroll
        for (int m=0;m<4;m++) {
            float4 v = make_float4(acc[m][0],acc[m][1],acc[m][2],acc[m][3]);
            *(float4*)&h_s[(r0+m)*FDIM + c0] = v;
            *(float4*)&h_out[(size_t)(abase+r0+m)*FDIM + c0] = v;
        }
    }
    __syncthreads();

    // ---- edge aggregation: aggT[f][i] ----
    {
        const float2* h2 = (const float2*)h_s;
        const float2* tab2 = (const float2*)tabW;
        const int f2 = tid & 63, r = tid >> 6;
        for (int it=0; it<8; it++) {
            int i = it*4 + r;
            float ax=0.f, ay=0.f;
            const int eb = i*31;
            for (int c=0;c<31;c++) {
                float fcv = fc_s[eb+c];
                if (fcv != 0.f) {
                    int j = (c<i) ? c : c+1;
                    float uu = u_s[eb+c];
                    int t0 = (int)uu; float fr = uu - (float)t0;
                    const float2* tp = tab2 + (size_t)t0*64 + f2;
                    float2 w0 = tp[0], w1 = tp[64];
                    float wx = fmaf(fr, w1.x-w0.x, w0.x);
                    float wy = fmaf(fr, w1.y-w0.y, w0.y);
                    float2 hv = h2[j*64+f2];
                    ax = fmaf(hv.x*fcv, wx, ax);
                    ay = fmaf(hv.y*fcv, wy, ay);
                }
            }
            aggT[(2*f2)*TSTRIDE + i]   = ax;
            aggT[(2*f2+1)*TSTRIDE + i] = ay;
        }
    }

    // ---- GEMM2: pre = agg@W1 + b1 ; sig2 -> global ; t2=ssp -> xT ----
    {
        float acc[4][4] = {};
        for (int k0=0;k0<FDIM;k0+=16) {
            __syncthreads();
            #pragma unroll
            for (int s=0;s<2;s++) {
                int i4 = tid + s*256;
                int row = i4>>5, c4 = (i4&31)<<2;
                *(float4*)&Ws[row*FDIM + c4] =
                    *(const float4*)&W1[(size_t)(k0+row)*FDIM + c4];
            }
            __syncthreads();
            #pragma unroll
            for (int kk=0;kk<16;kk++) {
                float4 a = *(float4*)&aggT[(k0+kk)*TSTRIDE + r0];
                float4 b = *(float4*)&Ws[kk*FDIM + c0];
                float av[4]={a.x,a.y,a.z,a.w}, bv[4]={b.x,b.y,b.z,b.w};
                #pragma unroll
                for (int m=0;m<4;m++)
                    #pragma unroll
                    for (int n=0;n<4;n++) acc[m][n] = fmaf(av[m], bv[n], acc[m][n]);
            }
        }
        float4 b1v = *(const float4*)&b1[c0];
        float bb[4]={b1v.x,b1v.y,b1v.z,b1v.w};
        __syncthreads();   // xT reads (GEMM1) long done; protect overwrite ordering
        #pragma unroll
        for (int m=0;m<4;m++) {
            float sg4[4];
            #pragma unroll
            for (int n=0;n<4;n++) {
                float pre = acc[m][n] + bb[n];
                float sg = 1.f/(1.f+expf(-pre));
                sg4[n] = sg;
                xT[(c0+n)*TSTRIDE + r0+m] = sspf(pre);
            }
            *(float4*)&sig2_out[(size_t)(abase+r0+m)*FDIM + c0] =
                make_float4(sg4[0],sg4[1],sg4[2],sg4[3]);
        }
    }

    // ---- GEMM3: x = x + t2@W2 + b2 ----
    {
        float acc[4][4] = {};
        for (int k0=0;k0<FDIM;k0+=16) {
            __syncthreads();
            #pragma unroll
            for (int s=0;s<2;s++) {
                int i4 = tid + s*256;
                int row = i4>>5, c4 = (i4&31)<<2;
                *(float4*)&Ws[row*FDIM + c4] =
                    *(const float4*)&W2[(size_t)(k0+row)*FDIM + c4];
            }
            __syncthreads();
            #pragma unroll
            for (int kk=0;kk<16;kk++) {
                float4 a = *(float4*)&xT[(k0+kk)*TSTRIDE + r0];
                float4 b = *(float4*)&Ws[kk*FDIM + c0];
                float av[4]={a.x,a.y,a.z,a.w}, bv[4]={b.x,b.y,b.z,b.w};
                #pragma unroll
                for (int m=0;m<4;m++)
                    #pragma unroll
                    for (int n=0;n<4;n++) acc[m][n] = fmaf(av[m], bv[n], acc[m][n]);
            }
        }
        float4 b2v = *(const float4*)&b2[c0];
        #pragma unroll
        for (int m=0;m<4;m++) {
            float4 xv = *(const float4*)&x_io[(size_t)(abase+r0+m)*FDIM + c0];
            xv.x += acc[m][0] + b2v.x;
            xv.y += acc[m][1] + b2v.y;
            xv.z += acc[m][2] + b2v.z;
            xv.w += acc[m][3] + b2v.w;
            *(float4*)&x_io[(size_t)(abase+r0+m)*FDIM + c0] = xv;
        }
    }
}

// =====================================================================
// Fused backward layer (one CTA per molecule, 256 threads)
//   gpre2 = (gx@W2^T)*sig2 ; ga = gpre2@W1^T ; edge bwd (gh, gd) ;
//   gx = gx + gh@W0^T
// =====================================================================
__global__ __launch_bounds__(256) void bwd_layer_k(
    float* __restrict__ gx_io, const float* __restrict__ W0,
    const float* __restrict__ W1, const float* __restrict__ W2,
    const float* __restrict__ sig2, const float* __restrict__ h_in,
    const float* __restrict__ tabW, const float* __restrict__ tabD,
    const float* __restrict__ fc, const float* __restrict__ dfc,
    const float* __restrict__ u, float* __restrict__ gd)
{
    extern __shared__ float sm[];
    float* gxT  = sm;                       // [128*TSTRIDE] (reused as ghT)
    float* tT   = gxT + FDIM*TSTRIDE;       // [128*TSTRIDE] gpre2T
    float* ga_s = tT + FDIM*TSTRIDE;        // [32*128]
    float* h_s  = ga_s + APM*FDIM;          // [32*128]
    float* Ws   = h_s + APM*FDIM;           // [16*128]
    float* fc_s = Ws + 16*FDIM;             // [992]
    float* dfc_s= fc_s + EPM;               // [992]
    float* u_s  = dfc_s + EPM;              // [992]
    float* gd_s = u_s + EPM;                // [992]

    const int tid = threadIdx.x;
    const int mol = blockIdx.x;
    const int abase = mol*APM;
    const size_t ebase = (size_t)mol*EPM;

    for (int t=tid; t<APM*FDIM/4; t+=256) {
        int a = t>>5, f4 = (t&31)<<2;
        float4 v = *(const float4*)&gx_io[(size_t)(abase+a)*FDIM + f4];
        gxT[(f4+0)*TSTRIDE+a]=v.x; gxT[(f4+1)*TSTRIDE+a]=v.y;
        gxT[(f4+2)*TSTRIDE+a]=v.z; gxT[(f4+3)*TSTRIDE+a]=v.w;
        float4 hv = *(const float4*)&h_in[(size_t)(abase+a)*FDIM + f4];
        *(float4*)&h_s[a*FDIM + f4] = hv;
    }
    for (int t=tid; t<EPM; t+=256) {
        fc_s[t]=fc[ebase+t]; dfc_s[t]=dfc[ebase+t]; u_s[t]=u[ebase+t]; gd_s[t]=0.f;
    }
    __syncthreads();

    const int rg = tid>>5, cg = tid&31;
    const int r0 = rg<<2, c0 = cg<<2;

    // ---- GEMM1: gpre2 = (gx @ W2^T) * sig2 -> tT (transposed) ----
    {
        float acc[4][4] = {};
        for (int k0=0;k0<FDIM;k0+=16) {
            __syncthreads();
            #pragma unroll
            for (int s=0;s<2;s++) {
                int i4 = tid + s*256;
                int c = i4>>2, kq = (i4&3)<<2;
                float4 w = *(const float4*)&W2[(size_t)c*FDIM + k0 + kq];
                Ws[(kq+0)*FDIM + c] = w.x;
                Ws[(kq+1)*FDIM + c] = w.y;
                Ws[(kq+2)*FDIM + c] = w.z;
                Ws[(kq+3)*FDIM + c] = w.w;
            }
            __syncthreads();
            #pragma unroll
            for (int kk=0;kk<16;kk++) {
                float4 a = *(float4*)&gxT[(k0+kk)*TSTRIDE + r0];
                float4 b = *(float4*)&Ws[kk*FDIM + c0];
                float av[4]={a.x,a.y,a.z,a.w}, bv[4]={b.x,b.y,b.z,b.w};
                #pragma unroll
                for (int m=0;m<4;m++)
                    #pragma unroll
                    for (int n=0;n<4;n++) acc[m][n] = fmaf(av[m], bv[n], acc[m][n]);
            }
        }
        #pragma unroll
        for (int m=0;m<4;m++) {
            float4 s4 = *(const float4*)&sig2[(size_t)(abase+r0+m)*FDIM + c0];
            float sv[4]={s4.x,s4.y,s4.z,s4.w};
            #pragma unroll
            for (int n=0;n<4;n++)
                tT[(c0+n)*TSTRIDE + r0+m] = acc[m][n]*sv[n];
        }
    }

    // ---- GEMM2: ga = gpre2 @ W1^T -> ga_s (normal) ----
    {
        float acc[4][4] = {};
        for (int k0=0;k0<FDIM;k0+=16) {
            __syncthreads();
            #pragma unroll
            for (int s=0;s<2;s++) {
                int i4 = tid + s*256;
                int c = i4>>2, kq = (i4&3)<<2;
                float4 w = *(const float4*)&W1[(size_t)c*FDIM + k0 + kq];
                Ws[(kq+0)*FDIM + c] = w.x;
                Ws[(kq+1)*FDIM + c] = w.y;
                Ws[(kq+2)*FDIM + c] = w.z;
                Ws[(kq+3)*FDIM + c] = w.w;
            }
            __syncthreads();
            #pragma unroll
            for (int kk=0;kk<16;kk++) {
                float4 a = *(float4*)&tT[(k0+kk)*TSTRIDE + r0];
                float4 b = *(float4*)&Ws[kk*FDIM + c0];
                float av[4]={a.x,a.y,a.z,a.w}, bv[4]={b.x,b.y,b.z,b.w};
                #pragma unroll
                for (int m=0;m<4;m++)
                    #pragma unroll
                    for (int n=0;n<4;n++) acc[m][n] = fmaf(av[m], bv[n], acc[m][n]);
            }
        }
        #pragma unroll
        for (int m=0;m<4;m++)
            *(float4*)&ga_s[(r0+m)*FDIM + c0] =
                make_float4(acc[m][0],acc[m][1],acc[m][2],acc[m][3]);
    }
    __syncthreads();

    // ---- edge backward: gh -> ghT(=gxT), gd_s ----
    {
        float* ghT = gxT;
        const float2* h2 = (const float2*)h_s;
        const float2* ga2 = (const float2*)ga_s;
        const float2* tw2 = (const float2*)tabW;
        const float2* td2 = (const float2*)tabD;
        const int f2 = tid & 63, r = tid >> 6, lane = tid & 31;
        for (int jt=0; jt<8; jt++) {
            int j = jt*4 + r;
            float2 hj = h2[j*64+f2];
            float ghx=0.f, ghy=0.f;
            for (int i=0;i<APM;i++) {
                if (i == j) continue;
                int el = i*31 + ((j<i)? j : j-1);
                float fcv = fc_s[el];
                if (fcv != 0.f) {
                    float uu = u_s[el]; int t0 = (int)uu; float fr = uu - (float)t0;
                    const float2* tw = tw2 + (size_t)t0*64 + f2;
                    const float2* td = td2 + (size_t)t0*64 + f2;
                    float2 w0=tw[0], w1=tw[64], d0=td[0], d1=td[64];
                    float wx=fmaf(fr,w1.x-w0.x,w0.x), wy=fmaf(fr,w1.y-w0.y,w0.y);
                    float dx=fmaf(fr,d1.x-d0.x,d0.x), dy=fmaf(fr,d1.y-d0.y,d0.y);
                    float2 ga = ga2[i*64+f2];
                    ghx = fmaf(ga.x*fcv, wx, ghx);
                    ghy = fmaf(ga.y*fcv, wy, ghy);
                    float dfcv = dfc_s[el];
                    float term = ga.x*hj.x*fmaf(dx,fcv,wx*dfcv)
                               + ga.y*hj.y*fmaf(dy,fcv,wy*dfcv);
                    #pragma unroll
                    for (int o=16;o>0;o>>=1)
                        term += __shfl_xor_sync(0xffffffffu, term, o);
                    if (lane == 0) atomicAdd(&gd_s[el], term);
                }
            }
            ghT[(2*f2)*TSTRIDE + j]   = ghx;
            ghT[(2*f2+1)*TSTRIDE + j] = ghy;
        }
    }

    // ---- GEMM3: gx += gh @ W0^T ----
    {
        float* ghT = gxT;
        float acc[4][4] = {};
        for (int k0=0;k0<FDIM;k0+=16) {
            __syncthreads();
            #pragma unroll
            for (int s=0;s<2;s++) {
                int i4 = tid + s*256;
                int c = i4>>2, kq = (i4&3)<<2;
                float4 w = *(const float4*)&W0[(size_t)c*FDIM + k0 + kq];
                Ws[(kq+0)*FDIM + c] = w.x;
                Ws[(kq+1)*FDIM + c] = w.y;
                Ws[(kq+2)*FDIM + c] = w.z;
                Ws[(kq+3)*FDIM + c] = w.w;
            }
            __syncthreads();
            #pragma unroll
            for (int kk=0;kk<16;kk++) {
                float4 a = *(float4*)&ghT[(k0+kk)*TSTRIDE + r0];
                float4 b = *(float4*)&Ws[kk*FDIM + c0];
                float av[4]={a.x,a.y,a.z,a.w}, bv[4]={b.x,b.y,b.z,b.w};
                #pragma unroll
                for (int m=0;m<4;m++)
                    #pragma unroll
                    for (int n=0;n<4;n++) acc[m][n] = fmaf(av[m], bv[n], acc[m][n]);
            }
        }
        #pragma unroll
        for (int m=0;m<4;m++) {
            float4 g = *(const float4*)&gx_io[(size_t)(abase+r0+m)*FDIM + c0];
            g.x += acc[m][0]; g.y += acc[m][1]; g.z += acc[m][2]; g.w += acc[m][3];
            *(float4*)&gx_io[(size_t)(abase+r0+m)*FDIM + c0] = g;
        }
    }
    __syncthreads();
    for (int el=tid; el<EPM; el+=256)
        gd[ebase+el] += gd_s[el];
}

// =====================================================================
// Fused head (fwd + bwd) per molecule, 256 threads, static smem
// =====================================================================
__global__ __launch_bounds__(256) void head_k(
    const float* __restrict__ x, const float* __restrict__ W1,
    const float* __restrict__ b1, const float* __restrict__ w2,
    const float* __restrict__ b2, float* __restrict__ out_energy,
    float* __restrict__ gx_out)
{
    __shared__ float xT[FDIM*TSTRIDE];
    __shared__ float gpT[FH*TSTRIDE];
    __shared__ float Ws[16*FDIM];
    __shared__ float es[APM];

    const int tid = threadIdx.x;
    const int mol = blockIdx.x;
    const int abase = mol*APM;

    for (int t=tid; t<APM*FDIM/4; t+=256) {
        int a = t>>5, f4 = (t&31)<<2;
        float4 v = *(const float4*)&x[(size_t)(abase+a)*FDIM + f4];
        xT[(f4+0)*TSTRIDE+a]=v.x; xT[(f4+1)*TSTRIDE+a]=v.y;
        xT[(f4+2)*TSTRIDE+a]=v.z; xT[(f4+3)*TSTRIDE+a]=v.w;
    }
    if (tid < APM) es[tid] = 0.f;
    __syncthreads();

    // ---- GEMMh: t = ssp(x@W1 + b1), gp = sig*w2, e parts ----
    {
        const int rg = tid>>5, cg = tid&31;
        const int r0 = rg<<2, c0 = cg<<1;
        float acc[4][2] = {};
        for (int k0=0;k0<FDIM;k0+=16) {
            __syncthreads();
            {
                int row = tid>>4, c4 = (tid&15)<<2;
                *(float4*)&Ws[row*FH + c4] =
                    *(const float4*)&W1[(size_t)(k0+row)*FH + c4];
            }
            __syncthreads();
            #pragma unroll
            for (int kk=0;kk<16;kk++) {
                float4 a = *(float4*)&xT[(k0+kk)*TSTRIDE + r0];
                float2 b = *(float2*)&Ws[kk*FH + c0];
                float av[4]={a.x,a.y,a.z,a.w};
                #pragma unroll
                for (int m=0;m<4;m++) {
                    acc[m][0] = fmaf(av[m], b.x, acc[m][0]);
                    acc[m][1] = fmaf(av[m], b.y, acc[m][1]);
                }
            }
        }
        float2 b1v = *(const float2*)&b1[c0];
        float2 w2v = *(const float2*)&w2[c0];
        float bb[2]={b1v.x,b1v.y}, ww[2]={w2v.x,w2v.y};
        #pragma unroll
        for (int m=0;m<4;m++) {
            float ep = 0.f;
            #pragma unroll
            for (int n=0;n<2;n++) {
                float pre = acc[m][n] + bb[n];
                float sg = 1.f/(1.f+expf(-pre));
                ep = fmaf(sspf(pre), ww[n], ep);
                gpT[(c0+n)*TSTRIDE + r0+m] = sg*ww[n];
            }
            atomicAdd(&es[r0+m], ep);
        }
    }
    __syncthreads();
    if (tid == 0) {
        float s = APM * b2[0];
        #pragma unroll
        for (int a=0;a<APM;a++) s += es[a];
        out_energy[mol] = s;
    }

    // ---- GEMM2h: gx = gp @ W1^T ----
    {
        const int rg = tid>>5, cg = tid&31;
        const int r0 = rg<<2, c0 = cg<<2;
        float acc[4][4] = {};
        for (int k0=0;k0<FH;k0+=16) {
            __syncthreads();
            #pragma unroll
            for (int s=0;s<2;s++) {
                int i4 = tid + s*256;
                int f = i4>>2, hq = (i4&3)<<2;
                float4 w = *(const float4*)&W1[(size_t)f*FH + k0 + hq];
                Ws[(hq+0)*FDIM + f] = w.x;
                Ws[(hq+1)*FDIM + f] = w.y;
                Ws[(hq+2)*FDIM + f] = w.z;
                Ws[(hq+3)*FDIM + f] = w.w;
            }
            __syncthreads();
            #pragma unroll
            for (int kk=0;kk<16;kk++) {
                float4 a = *(float4*)&gpT[(k0+kk)*TSTRIDE + r0];
                float4 b = *(float4*)&Ws[kk*FDIM + c0];
                float av[4]={a.x,a.y,a.z,a.w}, bv[4]={b.x,b.y,b.z,b.w};
                #pragma unroll
                for (int m=0;m<4;m++)
                    #pragma unroll
                    for (int n=0;n<4;n++) acc[m][n] = fmaf(av[m], bv[n], acc[m][n]);
            }
        }
        #pragma unroll
        for (int m=0;m<4;m++)
            *(float4*)&gx_out[(size_t)(abase+r0+m)*FDIM + c0] =
                make_float4(acc[m][0],acc[m][1],acc[m][2],acc[m][3]);
    }
}

// ---------------- final: grad_pos, clip, action ----------------
__global__ __launch_bounds__(256) void action_k(
    const float* __restrict__ pos, const float* __restrict__ gd,
    const float* __restrict__ dd, const int* __restrict__ ii,
    const int* __restrict__ jj, float* __restrict__ out)
{
    __shared__ float gp[APM*3];
    __shared__ float nrm[APM];
    __shared__ float coef_s;
    int mol = blockIdx.x, tid = threadIdx.x;
    int abase = mol*APM;
    size_t ebase = (size_t)mol*EPM;
    if (tid < APM*3) gp[tid] = 0.f;
    __syncthreads();
    for (int el=tid; el<EPM; el+=256) {
        size_t e = ebase + el;
        float g = gd[e];
        if (g != 0.f) {
            int i = ii[e], j = jj[e];
            float rx = pos[j*3+0]-pos[i*3+0];
            float ry = pos[j*3+1]-pos[i*3+1];
            float rz = pos[j*3+2]-pos[i*3+2];
            g /= dd[e];
            int jl = (j-abase)*3, il = (i-abase)*3;
            atomicAdd(&gp[jl+0],  g*rx); atomicAdd(&gp[jl+1],  g*ry); atomicAdd(&gp[jl+2],  g*rz);
            atomicAdd(&gp[il+0], -g*rx); atomicAdd(&gp[il+1], -g*ry); atomicAdd(&gp[il+2], -g*rz);
        }
    }
    __syncthreads();
    if (tid < APM) {
        float ax = gp[tid*3+0], ay = gp[tid*3+1], az = gp[tid*3+2];
        nrm[tid] = sqrtf(ax*ax + ay*ay + az*az);
    }
    __syncthreads();
    if (tid == 0) {
        float mx = 0.f;
        for (int a=0;a<APM;a++) mx = fmaxf(mx, nrm[a]);
        coef_s = fminf(1.0f / fmaxf(mx, 1e-8f), 1.0f);
    }
    __syncthreads();
    float cf = coef_s;
    for (int t=tid; t<APM*3; t+=256)
        out[(size_t)abase*3 + t] = -gp[t]*cf;
}

// ---------------- host ----------------
static const int FWD_SMEM = (FDIM*TSTRIDE*2 + APM*FDIM + 16*FDIM + 2*EPM) * 4;
static const int BWD_SMEM = (FDIM*TSTRIDE*2 + 2*APM*FDIM + 16*FDIM + 4*EPM) * 4;

extern "C" void kernel_launch(void* const* d_in, const int* in_sizes, int n_in,
                              void* d_out, int out_size)
{
    const float* positions = (const float*)d_in[0];
    const float* emb       = (const float*)d_in[1];
    const float* in2f_W    = (const float*)d_in[2];
    const float* filt_W1   = (const float*)d_in[3];
    const float* filt_b1   = (const float*)d_in[4];
    const float* filt_W2   = (const float*)d_in[5];
    const float* filt_b2   = (const float*)d_in[6];
    const float* f2_W1     = (const float*)d_in[7];
    const float* f2_b1     = (const float*)d_in[8];
    const float* f2_W2     = (const float*)d_in[9];
    const float* f2_b2     = (const float*)d_in[10];
    const float* aw_W1     = (const float*)d_in[11];
    const float* aw_b1     = (const float*)d_in[12];
    const float* aw_W2     = (const float*)d_in[13];
    const float* aw_b2     = (const float*)d_in[14];
    const int*   Z         = (const int*)d_in[15];
    const int*   idx_i     = (const int*)d_in[16];
    const int*   idx_j     = (const int*)d_in[17];
    float* out = (float*)d_out;

    float *p_x,*p_h,*p_sig2,*p_gx,*p_d,*p_fc,*p_dfc,*p_u,*p_gd,*p_tabW,*p_tabD;
    cudaGetSymbolAddress((void**)&p_x,    g_x);
    cudaGetSymbolAddress((void**)&p_h,    g_h);
    cudaGetSymbolAddress((void**)&p_sig2, g_sig2);
    cudaGetSymbolAddress((void**)&p_gx,   g_gx);
    cudaGetSymbolAddress((void**)&p_d,    g_d);
    cudaGetSymbolAddress((void**)&p_fc,   g_fc);
    cudaGetSymbolAddress((void**)&p_dfc,  g_dfc);
    cudaGetSymbolAddress((void**)&p_u,    g_u);
    cudaGetSymbolAddress((void**)&p_gd,   g_gd);
    cudaGetSymbolAddress((void**)&p_tabW, g_tabW);
    cudaGetSymbolAddress((void**)&p_tabD, g_tabD);

    cudaFuncSetAttribute(fwd_layer_k, cudaFuncAttributeMaxDynamicSharedMemorySize, FWD_SMEM);
    cudaFuncSetAttribute(bwd_layer_k, cudaFuncAttributeMaxDynamicSharedMemorySize, BWD_SMEM);

    table_k<<<dim3(TABN,3),128>>>(filt_W1, filt_b1, filt_W2, filt_b2, p_tabW, p_tabD);
    edge_pre_k<<<(int)((ETOT+255)/256),256>>>(positions, idx_i, idx_j,
                                              p_d, p_fc, p_dfc, p_u, p_gd);
    gather_emb_k<<<(NATOMS*FDIM+255)/256,256>>>(emb, Z, p_x);

    for (int l = 0; l < NLAY; l++) {
        fwd_layer_k<<<NMOL,256,FWD_SMEM>>>(
            p_x, in2f_W + (size_t)l*FDIM*FDIM,
            f2_W1 + (size_t)l*FDIM*FDIM, f2_b1 + l*FDIM,
            f2_W2 + (size_t)l*FDIM*FDIM, f2_b2 + l*FDIM,
            p_tabW + (size_t)l*TABN*FDIM,
            p_fc, p_u,
            p_h + (size_t)l*NF, p_sig2 + (size_t)l*NF);
    }

    head_k<<<NMOL,256>>>(p_x, aw_W1, aw_b1, aw_W2, aw_b2,
                         out + (size_t)3*NATOMS, p_gx);

    for (int l = NLAY-1; l >= 0; l--) {
        bwd_layer_k<<<NMOL,256,BWD_SMEM>>>(
            p_gx, in2f_W + (size_t)l*FDIM*FDIM,
            f2_W1 + (size_t)l*FDIM*FDIM, f2_W2 + (size_t)l*FDIM*FDIM,
            p_sig2 + (size_t)l*NF, p_h + (size_t)l*NF,
            p_tabW + (size_t)l*TABN*FDIM, p_tabD + (size_t)l*TABN*FDIM,
            p_fc, p_dfc, p_u, p_gd);
    }

    action_k<<<NMOL,256>>>(positions, p_gd, p_d, idx_i, idx_j, out);
}

// round 4
// speedup vs baseline: 6.6539x; 1.1019x over previous
#include <cuda_runtime.h>
#include <math.h>

// ---------------- problem constants ----------------
#define NATOMS 16384
#define NMOL   512
#define APM    32
#define EPM    992
#define FDIM   128
#define NRBF   20
#define FH     64
#define NLAY   3
#define PI_F   3.14159265358979f
#define CUT    5.0f
#define LOG2_F 0.6931471805599453f
#define TABN   4096
#define ETOT_C 507904
#define TSTRIDE 36

static const long long ETOT = (long long)NMOL * EPM;
static const size_t NF = (size_t)NATOMS * FDIM;

// ---------------- scratch ----------------
__device__ __align__(16) float g_x    [NF];
__device__ __align__(16) float g_h    [3 * NF];
__device__ __align__(16) float g_sig2 [3 * NF];
__device__ __align__(16) float g_gx   [NF];
__device__ __align__(16) float g_d    [ETOT_C];
__device__ __align__(16) float g_fc   [ETOT_C];
__device__ __align__(16) float g_dfc  [ETOT_C];
__device__ __align__(16) float g_u    [ETOT_C];
__device__ __align__(16) float g_gd   [ETOT_C];
__device__ __align__(16) float g_tabW [3 * TABN * FDIM];
__device__ __align__(16) float g_tabD [3 * TABN * FDIM];

__device__ __forceinline__ float sspf(float v) {
    return fmaxf(v, 0.f) + log1pf(expf(-fabsf(v))) - LOG2_F;
}

// ---------------- filter table build ----------------
__global__ __launch_bounds__(128) void table_k(
    const float* __restrict__ W1, const float* __restrict__ b1,
    const float* __restrict__ W2, const float* __restrict__ b2,
    float* __restrict__ tabW, float* __restrict__ tabD)
{
    const int t = blockIdx.x;
    const int l = blockIdx.y;
    const int f = threadIdx.x;
    const float DELTA = CUT / (NRBF-1);
    const float CO = -0.5f / (DELTA*DELTA);
    const float d = t * (CUT / (TABN-1));

    __shared__ float rbf_s[NRBF], drbf_s[NRBF];
    __shared__ float t1_s[FDIM], dt1_s[FDIM];
    if (f < NRBF) {
        float u = d - f*DELTA;
        float g = expf(CO*u*u);
        rbf_s[f]  = g;
        drbf_s[f] = g * (2.f*CO*u);
    }
    __syncthreads();

    const float* W1l = W1 + (size_t)l*NRBF*FDIM;
    float p = b1[l*FDIM + f], dp = 0.f;
    #pragma unroll
    for (int k=0;k<NRBF;k++) {
        float w = W1l[k*FDIM + f];
        p  = fmaf(rbf_s[k],  w, p);
        dp = fmaf(drbf_s[k], w, dp);
    }
    float sg = 1.f/(1.f+expf(-p));
    t1_s[f]  = sspf(p);
    dt1_s[f] = sg*dp;
    __syncthreads();

    const float* W2l = W2 + (size_t)l*FDIM*FDIM;
    float w = b2[l*FDIM + f], dw = 0.f;
    #pragma unroll 8
    for (int c=0;c<FDIM;c++) {
        float wv = W2l[c*FDIM + f];
        w  = fmaf(t1_s[c],  wv, w);
        dw = fmaf(dt1_s[c], wv, dw);
    }
    size_t o = ((size_t)l*TABN + t)*FDIM + f;
    tabW[o] = w;
    tabD[o] = dw;
}

// ---------------- edge precompute ----------------
__global__ void edge_pre_k(const float* __restrict__ pos,
                           const int* __restrict__ ii, const int* __restrict__ jj,
                           float* __restrict__ dd, float* __restrict__ fc,
                           float* __restrict__ dfc, float* __restrict__ uu,
                           float* __restrict__ gd)
{
    long long e = (long long)blockIdx.x * blockDim.x + threadIdx.x;
    if (e >= ETOT) return;
    int i = ii[e], j = jj[e];
    float rx = pos[j*3+0]-pos[i*3+0];
    float ry = pos[j*3+1]-pos[i*3+1];
    float rz = pos[j*3+2]-pos[i*3+2];
    float d = sqrtf(rx*rx+ry*ry+rz*rz + 1e-12f);
    dd[e] = d;
    gd[e] = 0.f;
    if (d < CUT) {
        fc[e]  = 0.5f*(cosf(PI_F*d/CUT)+1.f);
        dfc[e] = (-0.5f*PI_F/CUT)*sinf(PI_F*d/CUT);
        float u = d * ((TABN-1)/CUT);
        uu[e] = fminf(u, (float)(TABN-2) + 0.9999f);
    } else {
        fc[e] = 0.f; dfc[e] = 0.f; uu[e] = 0.f;
    }
}

__global__ void gather_emb_k(const float* __restrict__ emb, const int* __restrict__ Z,
                             float* __restrict__ x)
{
    int idx = blockIdx.x*256 + threadIdx.x;
    if (idx >= NATOMS*FDIM) return;
    int n = idx >> 7, f = idx & 127;
    x[idx] = emb[(size_t)Z[n]*FDIM + f];
}

// =====================================================================
// Fused forward layer (one CTA per molecule, 512 threads)
// =====================================================================
__global__ __launch_bounds__(512) void fwd_layer_k(
    float* __restrict__ x_io, const float* __restrict__ W0,
    const float* __restrict__ W1, const float* __restrict__ b1,
    const float* __restrict__ W2, const float* __restrict__ b2,
    const float* __restrict__ tabW,
    const float* __restrict__ fc, const float* __restrict__ u,
    float* __restrict__ h_out, float* __restrict__ sig2_out)
{
    extern __shared__ float sm[];
    float* xT   = sm;                       // [128*TSTRIDE] (reused as t2T)
    float* h_s  = xT + FDIM*TSTRIDE;        // [32*128]
    float* aggT = h_s + APM*FDIM;           // [128*TSTRIDE]
    float* Ws   = aggT + FDIM*TSTRIDE;      // [16*128]
    float* fc_s = Ws + 16*FDIM;             // [992]
    float* u_s  = fc_s + EPM;               // [992]

    const int tid = threadIdx.x;
    const int mol = blockIdx.x;
    const int abase = mol*APM;
    const size_t ebase = (size_t)mol*EPM;

    for (int t=tid; t<APM*FDIM/4; t+=512) {
        int a = t>>5, f4 = (t&31)<<2;
        float4 v = *(const float4*)&x_io[(size_t)(abase+a)*FDIM + f4];
        xT[(f4+0)*TSTRIDE+a]=v.x; xT[(f4+1)*TSTRIDE+a]=v.y;
        xT[(f4+2)*TSTRIDE+a]=v.z; xT[(f4+3)*TSTRIDE+a]=v.w;
    }
    for (int t=tid; t<EPM; t+=512) { fc_s[t]=fc[ebase+t]; u_s[t]=u[ebase+t]; }
    __syncthreads();

    const int rg = tid>>5, cg = tid&31;
    const int r0 = rg<<1, c0 = cg<<2;    // 2x4 tile

    // ---- GEMM1: h = x @ W0 ----
    {
        float acc[2][4] = {};
        for (int k0=0;k0<FDIM;k0+=16) {
            __syncthreads();
            {
                int row = tid>>5, c4 = (tid&31)<<2;
                *(float4*)&Ws[row*FDIM + c4] =
                    *(const float4*)&W0[(size_t)(k0+row)*FDIM + c4];
            }
            __syncthreads();
            #pragma unroll
            for (int kk=0;kk<16;kk++) {
                float2 a = *(float2*)&xT[(k0+kk)*TSTRIDE + r0];
                float4 b = *(float4*)&Ws[kk*FDIM + c0];
                float av[2]={a.x,a.y}, bv[4]={b.x,b.y,b.z,b.w};
                #pragma unroll
                for (int m=0;m<2;m++)
                    #pragma unroll
                    for (int n=0;n<4;n++) acc[m][n] = fmaf(av[m], bv[n], acc[m][n]);
            }
        }
        #pragma unroll
        for (int m=0;m<2;m++) {
            float4 v = make_float4(acc[m][0],acc[m][1],acc[m][2],acc[m][3]);
            *(float4*)&h_s[(r0+m)*FDIM + c0] = v;
            *(float4*)&h_out[(size_t)(abase+r0+m)*FDIM + c0] = v;
        }
    }
    __syncthreads();

    // ---- edge aggregation: aggT[f][i] ----
    {
        const float2* h2 = (const float2*)h_s;
        const float2* tab2 = (const float2*)tabW;
        const int f2 = tid & 63, r = tid >> 6;
        for (int it=0; it<4; it++) {
            int i = it*8 + r;
            float ax=0.f, ay=0.f;
            const int eb = i*31;
            for (int c=0;c<31;c++) {
                float fcv = fc_s[eb+c];
                if (fcv != 0.f) {
                    int j = (c<i) ? c : c+1;
                    float uu = u_s[eb+c];
                    int t0 = (int)uu; float fr = uu - (float)t0;
                    const float2* tp = tab2 + (size_t)t0*64 + f2;
                    float2 w0 = tp[0], w1 = tp[64];
                    float wx = fmaf(fr, w1.x-w0.x, w0.x);
                    float wy = fmaf(fr, w1.y-w0.y, w0.y);
                    float2 hv = h2[j*64+f2];
                    ax = fmaf(hv.x*fcv, wx, ax);
                    ay = fmaf(hv.y*fcv, wy, ay);
                }
            }
            aggT[(2*f2)*TSTRIDE + i]   = ax;
            aggT[(2*f2+1)*TSTRIDE + i] = ay;
        }
    }

    // ---- GEMM2: pre = agg@W1 + b1 ; sig2 out ; t2=ssp -> xT ----
    {
        float acc[2][4] = {};
        for (int k0=0;k0<FDIM;k0+=16) {
            __syncthreads();
            {
                int row = tid>>5, c4 = (tid&31)<<2;
                *(float4*)&Ws[row*FDIM + c4] =
                    *(const float4*)&W1[(size_t)(k0+row)*FDIM + c4];
            }
            __syncthreads();
            #pragma unroll
            for (int kk=0;kk<16;kk++) {
                float2 a = *(float2*)&aggT[(k0+kk)*TSTRIDE + r0];
                float4 b = *(float4*)&Ws[kk*FDIM + c0];
                float av[2]={a.x,a.y}, bv[4]={b.x,b.y,b.z,b.w};
                #pragma unroll
                for (int m=0;m<2;m++)
                    #pragma unroll
                    for (int n=0;n<4;n++) acc[m][n] = fmaf(av[m], bv[n], acc[m][n]);
            }
        }
        float4 b1v = *(const float4*)&b1[c0];
        float bb[4]={b1v.x,b1v.y,b1v.z,b1v.w};
        __syncthreads();
        #pragma unroll
        for (int m=0;m<2;m++) {
            float sg4[4];
            #pragma unroll
            for (int n=0;n<4;n++) {
                float pre = acc[m][n] + bb[n];
                float sg = 1.f/(1.f+expf(-pre));
                sg4[n] = sg;
                xT[(c0+n)*TSTRIDE + r0+m] = sspf(pre);
            }
            *(float4*)&sig2_out[(size_t)(abase+r0+m)*FDIM + c0] =
                make_float4(sg4[0],sg4[1],sg4[2],sg4[3]);
        }
    }

    // ---- GEMM3: x = x + t2@W2 + b2 ----
    {
        float acc[2][4] = {};
        for (int k0=0;k0<FDIM;k0+=16) {
            __syncthreads();
            {
                int row = tid>>5, c4 = (tid&31)<<2;
                *(float4*)&Ws[row*FDIM + c4] =
                    *(const float4*)&W2[(size_t)(k0+row)*FDIM + c4];
            }
            __syncthreads();
            #pragma unroll
            for (int kk=0;kk<16;kk++) {
                float2 a = *(float2*)&xT[(k0+kk)*TSTRIDE + r0];
                float4 b = *(float4*)&Ws[kk*FDIM + c0];
                float av[2]={a.x,a.y}, bv[4]={b.x,b.y,b.z,b.w};
                #pragma unroll
                for (int m=0;m<2;m++)
                    #pragma unroll
                    for (int n=0;n<4;n++) acc[m][n] = fmaf(av[m], bv[n], acc[m][n]);
            }
        }
        float4 b2v = *(const float4*)&b2[c0];
        #pragma unroll
        for (int m=0;m<2;m++) {
            float4 xv = *(const float4*)&x_io[(size_t)(abase+r0+m)*FDIM + c0];
            xv.x += acc[m][0] + b2v.x;
            xv.y += acc[m][1] + b2v.y;
            xv.z += acc[m][2] + b2v.z;
            xv.w += acc[m][3] + b2v.w;
            *(float4*)&x_io[(size_t)(abase+r0+m)*FDIM + c0] = xv;
        }
    }
}

// =====================================================================
// Fused backward layer (one CTA per molecule, 512 threads)
//   gpre2 = (gx@W2^T)*sig2 ; ga = gpre2@W1^T ;
//   gh phase (no shuffles) ; gd phase (warp-per-edge, no atomics) ;
//   gx += gh@W0^T
// =====================================================================
__global__ __launch_bounds__(512) void bwd_layer_k(
    float* __restrict__ gx_io, const float* __restrict__ W0,
    const float* __restrict__ W1, const float* __restrict__ W2,
    const float* __restrict__ sig2, const float* __restrict__ h_in,
    const float* __restrict__ tabW, const float* __restrict__ tabD,
    const float* __restrict__ fc, const float* __restrict__ dfc,
    const float* __restrict__ u, float* __restrict__ gd)
{
    extern __shared__ float sm[];
    float* gxT  = sm;                       // [128*TSTRIDE] (reused as ghT)
    float* tT   = gxT + FDIM*TSTRIDE;       // [128*TSTRIDE]
    float* ga_s = tT + FDIM*TSTRIDE;        // [32*128]
    float* h_s  = ga_s + APM*FDIM;          // [32*128]
    float* Ws   = h_s + APM*FDIM;           // [16*128]
    float* fc_s = Ws + 16*FDIM;             // [992]
    float* dfc_s= fc_s + EPM;               // [992]
    float* u_s  = dfc_s + EPM;              // [992]

    const int tid = threadIdx.x;
    const int mol = blockIdx.x;
    const int abase = mol*APM;
    const size_t ebase = (size_t)mol*EPM;

    for (int t=tid; t<APM*FDIM/4; t+=512) {
        int a = t>>5, f4 = (t&31)<<2;
        float4 v = *(const float4*)&gx_io[(size_t)(abase+a)*FDIM + f4];
        gxT[(f4+0)*TSTRIDE+a]=v.x; gxT[(f4+1)*TSTRIDE+a]=v.y;
        gxT[(f4+2)*TSTRIDE+a]=v.z; gxT[(f4+3)*TSTRIDE+a]=v.w;
        float4 hv = *(const float4*)&h_in[(size_t)(abase+a)*FDIM + f4];
        *(float4*)&h_s[a*FDIM + f4] = hv;
    }
    for (int t=tid; t<EPM; t+=512) {
        fc_s[t]=fc[ebase+t]; dfc_s[t]=dfc[ebase+t]; u_s[t]=u[ebase+t];
    }
    __syncthreads();

    const int rg = tid>>5, cg = tid&31;
    const int r0 = rg<<1, c0 = cg<<2;

    // ---- GEMM1: gpre2 = (gx @ W2^T)*sig2 -> tT (transposed) ----
    {
        float acc[2][4] = {};
        for (int k0=0;k0<FDIM;k0+=16) {
            __syncthreads();
            {
                int c = tid>>2, kq = (tid&3)<<2;
                float4 w = *(const float4*)&W2[(size_t)c*FDIM + k0 + kq];
                Ws[(kq+0)*FDIM + c] = w.x;
                Ws[(kq+1)*FDIM + c] = w.y;
                Ws[(kq+2)*FDIM + c] = w.z;
                Ws[(kq+3)*FDIM + c] = w.w;
            }
            __syncthreads();
            #pragma unroll
            for (int kk=0;kk<16;kk++) {
                float2 a = *(float2*)&gxT[(k0+kk)*TSTRIDE + r0];
                float4 b = *(float4*)&Ws[kk*FDIM + c0];
                float av[2]={a.x,a.y}, bv[4]={b.x,b.y,b.z,b.w};
                #pragma unroll
                for (int m=0;m<2;m++)
                    #pragma unroll
                    for (int n=0;n<4;n++) acc[m][n] = fmaf(av[m], bv[n], acc[m][n]);
            }
        }
        #pragma unroll
        for (int m=0;m<2;m++) {
            float4 s4 = *(const float4*)&sig2[(size_t)(abase+r0+m)*FDIM + c0];
            float sv[4]={s4.x,s4.y,s4.z,s4.w};
            #pragma unroll
            for (int n=0;n<4;n++)
                tT[(c0+n)*TSTRIDE + r0+m] = acc[m][n]*sv[n];
        }
    }

    // ---- GEMM2: ga = gpre2 @ W1^T -> ga_s ----
    {
        float acc[2][4] = {};
        for (int k0=0;k0<FDIM;k0+=16) {
            __syncthreads();
            {
                int c = tid>>2, kq = (tid&3)<<2;
                float4 w = *(const float4*)&W1[(size_t)c*FDIM + k0 + kq];
                Ws[(kq+0)*FDIM + c] = w.x;
                Ws[(kq+1)*FDIM + c] = w.y;
                Ws[(kq+2)*FDIM + c] = w.z;
                Ws[(kq+3)*FDIM + c] = w.w;
            }
            __syncthreads();
            #pragma unroll
            for (int kk=0;kk<16;kk++) {
                float2 a = *(float2*)&tT[(k0+kk)*TSTRIDE + r0];
                float4 b = *(float4*)&Ws[kk*FDIM + c0];
                float av[2]={a.x,a.y}, bv[4]={b.x,b.y,b.z,b.w};
                #pragma unroll
                for (int m=0;m<2;m++)
                    #pragma unroll
                    for (int n=0;n<4;n++) acc[m][n] = fmaf(av[m], bv[n], acc[m][n]);
            }
        }
        #pragma unroll
        for (int m=0;m<2;m++)
            *(float4*)&ga_s[(r0+m)*FDIM + c0] =
                make_float4(acc[m][0],acc[m][1],acc[m][2],acc[m][3]);
    }
    __syncthreads();

    // ---- gh phase: ghT[f][j] = sum_i ga[i,f]*fc*W (no shuffles) ----
    {
        float* ghT = gxT;
        const float2* h2 = (const float2*)h_s;   (void)h2;
        const float2* ga2 = (const float2*)ga_s;
        const float2* tab2 = (const float2*)tabW;
        const int f2 = tid & 63, r = tid >> 6;
        for (int jt=0; jt<4; jt++) {
            int j = jt*8 + r;
            float ghx=0.f, ghy=0.f;
            for (int i=0;i<APM;i++) {
                if (i == j) continue;
                int el = i*31 + ((j<i)? j : j-1);
                float fcv = fc_s[el];
                if (fcv != 0.f) {
                    float uu = u_s[el]; int t0 = (int)uu; float fr = uu - (float)t0;
                    const float2* tp = tab2 + (size_t)t0*64 + f2;
                    float2 w0 = tp[0], w1 = tp[64];
                    float wx = fmaf(fr, w1.x-w0.x, w0.x);
                    float wy = fmaf(fr, w1.y-w0.y, w0.y);
                    float2 ga = ga2[i*64+f2];
                    ghx = fmaf(ga.x*fcv, wx, ghx);
                    ghy = fmaf(ga.y*fcv, wy, ghy);
                }
            }
            ghT[(2*f2)*TSTRIDE + j]   = ghx;
            ghT[(2*f2+1)*TSTRIDE + j] = ghy;
        }
    }

    // ---- gd phase: warp-per-edge, coalesced table rows, no atomics ----
    {
        const int warp = tid >> 5, lane = tid & 31;
        for (int el = warp; el < EPM; el += 16) {
            float fcv = fc_s[el];
            if (fcv == 0.f) continue;
            int i = el / 31;
            int c = el - i*31;
            int j = c + (c >= i ? 1 : 0);
            float uu = u_s[el]; int t0 = (int)uu; float fr = uu - (float)t0;
            const float4* tw = (const float4*)(tabW + (size_t)t0*FDIM) + lane;
            const float4* td = (const float4*)(tabD + (size_t)t0*FDIM) + lane;
            float4 w0 = tw[0], w1 = tw[32];
            float4 d0 = td[0], d1 = td[32];
            float4 ga = *(const float4*)&ga_s[i*FDIM + (lane<<2)];
            float4 hv = *(const float4*)&h_s[j*FDIM + (lane<<2)];
            float p0 = ga.x*hv.x, p1 = ga.y*hv.y, p2 = ga.z*hv.z, p3 = ga.w*hv.w;
            float sW = p0*fmaf(fr,w1.x-w0.x,w0.x) + p1*fmaf(fr,w1.y-w0.y,w0.y)
                     + p2*fmaf(fr,w1.z-w0.z,w0.z) + p3*fmaf(fr,w1.w-w0.w,w0.w);
            float sD = p0*fmaf(fr,d1.x-d0.x,d0.x) + p1*fmaf(fr,d1.y-d0.y,d0.y)
                     + p2*fmaf(fr,d1.z-d0.z,d0.z) + p3*fmaf(fr,d1.w-d0.w,d0.w);
            float term = fmaf(fcv, sD, dfc_s[el]*sW);
            #pragma unroll
            for (int o=16;o>0;o>>=1) term += __shfl_xor_sync(0xffffffffu, term, o);
            if (lane == 0) gd[ebase+el] += term;
        }
    }

    // ---- GEMM3: gx += gh @ W0^T ----
    {
        float* ghT = gxT;
        float acc[2][4] = {};
        for (int k0=0;k0<FDIM;k0+=16) {
            __syncthreads();
            {
                int c = tid>>2, kq = (tid&3)<<2;
                float4 w = *(const float4*)&W0[(size_t)c*FDIM + k0 + kq];
                Ws[(kq+0)*FDIM + c] = w.x;
                Ws[(kq+1)*FDIM + c] = w.y;
                Ws[(kq+2)*FDIM + c] = w.z;
                Ws[(kq+3)*FDIM + c] = w.w;
            }
            __syncthreads();
            #pragma unroll
            for (int kk=0;kk<16;kk++) {
                float2 a = *(float2*)&ghT[(k0+kk)*TSTRIDE + r0];
                float4 b = *(float4*)&Ws[kk*FDIM + c0];
                float av[2]={a.x,a.y}, bv[4]={b.x,b.y,b.z,b.w};
                #pragma unroll
                for (int m=0;m<2;m++)
                    #pragma unroll
                    for (int n=0;n<4;n++) acc[m][n] = fmaf(av[m], bv[n], acc[m][n]);
            }
        }
        #pragma unroll
        for (int m=0;m<2;m++) {
            float4 g = *(const float4*)&gx_io[(size_t)(abase+r0+m)*FDIM + c0];
            g.x += acc[m][0]; g.y += acc[m][1]; g.z += acc[m][2]; g.w += acc[m][3];
            *(float4*)&gx_io[(size_t)(abase+r0+m)*FDIM + c0] = g;
        }
    }
}

// =====================================================================
// Fused head (fwd + bwd) per molecule, 256 threads
// =====================================================================
__global__ __launch_bounds__(256) void head_k(
    const float* __restrict__ x, const float* __restrict__ W1,
    const float* __restrict__ b1, const float* __restrict__ w2,
    const float* __restrict__ b2, float* __restrict__ out_energy,
    float* __restrict__ gx_out)
{
    __shared__ float xT[FDIM*TSTRIDE];
    __shared__ float gpT[FH*TSTRIDE];
    __shared__ float Ws[16*FDIM];
    __shared__ float es[APM];

    const int tid = threadIdx.x;
    const int mol = blockIdx.x;
    const int abase = mol*APM;

    for (int t=tid; t<APM*FDIM/4; t+=256) {
        int a = t>>5, f4 = (t&31)<<2;
        float4 v = *(const float4*)&x[(size_t)(abase+a)*FDIM + f4];
        xT[(f4+0)*TSTRIDE+a]=v.x; xT[(f4+1)*TSTRIDE+a]=v.y;
        xT[(f4+2)*TSTRIDE+a]=v.z; xT[(f4+3)*TSTRIDE+a]=v.w;
    }
    if (tid < APM) es[tid] = 0.f;
    __syncthreads();

    {
        const int rg = tid>>5, cg = tid&31;
        const int r0 = rg<<2, c0 = cg<<1;
        float acc[4][2] = {};
        for (int k0=0;k0<FDIM;k0+=16) {
            __syncthreads();
            {
                int row = tid>>4, c4 = (tid&15)<<2;
                *(float4*)&Ws[row*FH + c4] =
                    *(const float4*)&W1[(size_t)(k0+row)*FH + c4];
            }
            __syncthreads();
            #pragma unroll
            for (int kk=0;kk<16;kk++) {
                float4 a = *(float4*)&xT[(k0+kk)*TSTRIDE + r0];
                float2 b = *(float2*)&Ws[kk*FH + c0];
                float av[4]={a.x,a.y,a.z,a.w};
                #pragma unroll
                for (int m=0;m<4;m++) {
                    acc[m][0] = fmaf(av[m], b.x, acc[m][0]);
                    acc[m][1] = fmaf(av[m], b.y, acc[m][1]);
                }
            }
        }
        float2 b1v = *(const float2*)&b1[c0];
        float2 w2v = *(const float2*)&w2[c0];
        float bb[2]={b1v.x,b1v.y}, ww[2]={w2v.x,w2v.y};
        #pragma unroll
        for (int m=0;m<4;m++) {
            float ep = 0.f;
            #pragma unroll
            for (int n=0;n<2;n++) {
                float pre = acc[m][n] + bb[n];
                float sg = 1.f/(1.f+expf(-pre));
                ep = fmaf(sspf(pre), ww[n], ep);
                gpT[(c0+n)*TSTRIDE + r0+m] = sg*ww[n];
            }
            atomicAdd(&es[r0+m], ep);
        }
    }
    __syncthreads();
    if (tid == 0) {
        float s = APM * b2[0];
        #pragma unroll
        for (int a=0;a<APM;a++) s += es[a];
        out_energy[mol] = s;
    }

    {
        const int rg = tid>>5, cg = tid&31;
        const int r0 = rg<<2, c0 = cg<<2;
        float acc[4][4] = {};
        for (int k0=0;k0<FH;k0+=16) {
            __syncthreads();
            #pragma unroll
            for (int s=0;s<2;s++) {
                int i4 = tid + s*256;
                int f = i4>>2, hq = (i4&3)<<2;
                float4 w = *(const float4*)&W1[(size_t)f*FH + k0 + hq];
                Ws[(hq+0)*FDIM + f] = w.x;
                Ws[(hq+1)*FDIM + f] = w.y;
                Ws[(hq+2)*FDIM + f] = w.z;
                Ws[(hq+3)*FDIM + f] = w.w;
            }
            __syncthreads();
            #pragma unroll
            for (int kk=0;kk<16;kk++) {
                float4 a = *(float4*)&gpT[(k0+kk)*TSTRIDE + r0];
                float4 b = *(float4*)&Ws[kk*FDIM + c0];
                float av[4]={a.x,a.y,a.z,a.w}, bv[4]={b.x,b.y,b.z,b.w};
                #pragma unroll
                for (int m=0;m<4;m++)
                    #pragma unroll
                    for (int n=0;n<4;n++) acc[m][n] = fmaf(av[m], bv[n], acc[m][n]);
            }
        }
        #pragma unroll
        for (int m=0;m<4;m++)
            *(float4*)&gx_out[(size_t)(abase+r0+m)*FDIM + c0] =
                make_float4(acc[m][0],acc[m][1],acc[m][2],acc[m][3]);
    }
}

// ---------------- final: grad_pos, clip, action ----------------
__global__ __launch_bounds__(256) void action_k(
    const float* __restrict__ pos, const float* __restrict__ gd,
    const float* __restrict__ dd, const int* __restrict__ ii,
    const int* __restrict__ jj, float* __restrict__ out)
{
    __shared__ float gp[APM*3];
    __shared__ float nrm[APM];
    __shared__ float coef_s;
    int mol = blockIdx.x, tid = threadIdx.x;
    int abase = mol*APM;
    size_t ebase = (size_t)mol*EPM;
    if (tid < APM*3) gp[tid] = 0.f;
    __syncthreads();
    for (int el=tid; el<EPM; el+=256) {
        size_t e = ebase + el;
        float g = gd[e];
        if (g != 0.f) {
            int i = ii[e], j = jj[e];
            float rx = pos[j*3+0]-pos[i*3+0];
            float ry = pos[j*3+1]-pos[i*3+1];
            float rz = pos[j*3+2]-pos[i*3+2];
            g /= dd[e];
            int jl = (j-abase)*3, il = (i-abase)*3;
            atomicAdd(&gp[jl+0],  g*rx); atomicAdd(&gp[jl+1],  g*ry); atomicAdd(&gp[jl+2],  g*rz);
            atomicAdd(&gp[il+0], -g*rx); atomicAdd(&gp[il+1], -g*ry); atomicAdd(&gp[il+2], -g*rz);
        }
    }
    __syncthreads();
    if (tid < APM) {
        float ax = gp[tid*3+0], ay = gp[tid*3+1], az = gp[tid*3+2];
        nrm[tid] = sqrtf(ax*ax + ay*ay + az*az);
    }
    __syncthreads();
    if (tid == 0) {
        float mx = 0.f;
        for (int a=0;a<APM;a++) mx = fmaxf(mx, nrm[a]);
        coef_s = fminf(1.0f / fmaxf(mx, 1e-8f), 1.0f);
    }
    __syncthreads();
    float cf = coef_s;
    for (int t=tid; t<APM*3; t+=256)
        out[(size_t)abase*3 + t] = -gp[t]*cf;
}

// ---------------- host ----------------
static const int FWD_SMEM = (FDIM*TSTRIDE*2 + APM*FDIM + 16*FDIM + 2*EPM) * 4;
static const int BWD_SMEM = (FDIM*TSTRIDE*2 + 2*APM*FDIM + 16*FDIM + 3*EPM) * 4;

extern "C" void kernel_launch(void* const* d_in, const int* in_sizes, int n_in,
                              void* d_out, int out_size)
{
    const float* positions = (const float*)d_in[0];
    const float* emb       = (const float*)d_in[1];
    const float* in2f_W    = (const float*)d_in[2];
    const float* filt_W1   = (const float*)d_in[3];
    const float* filt_b1   = (const float*)d_in[4];
    const float* filt_W2   = (const float*)d_in[5];
    const float* filt_b2   = (const float*)d_in[6];
    const float* f2_W1     = (const float*)d_in[7];
    const float* f2_b1     = (const float*)d_in[8];
    const float* f2_W2     = (const float*)d_in[9];
    const float* f2_b2     = (const float*)d_in[10];
    const float* aw_W1     = (const float*)d_in[11];
    const float* aw_b1     = (const float*)d_in[12];
    const float* aw_W2     = (const float*)d_in[13];
    const float* aw_b2     = (const float*)d_in[14];
    const int*   Z         = (const int*)d_in[15];
    const int*   idx_i     = (const int*)d_in[16];
    const int*   idx_j     = (const int*)d_in[17];
    float* out = (float*)d_out;

    float *p_x,*p_h,*p_sig2,*p_gx,*p_d,*p_fc,*p_dfc,*p_u,*p_gd,*p_tabW,*p_tabD;
    cudaGetSymbolAddress((void**)&p_x,    g_x);
    cudaGetSymbolAddress((void**)&p_h,    g_h);
    cudaGetSymbolAddress((void**)&p_sig2, g_sig2);
    cudaGetSymbolAddress((void**)&p_gx,   g_gx);
    cudaGetSymbolAddress((void**)&p_d,    g_d);
    cudaGetSymbolAddress((void**)&p_fc,   g_fc);
    cudaGetSymbolAddress((void**)&p_dfc,  g_dfc);
    cudaGetSymbolAddress((void**)&p_u,    g_u);
    cudaGetSymbolAddress((void**)&p_gd,   g_gd);
    cudaGetSymbolAddress((void**)&p_tabW, g_tabW);
    cudaGetSymbolAddress((void**)&p_tabD, g_tabD);

    cudaFuncSetAttribute(fwd_layer_k, cudaFuncAttributeMaxDynamicSharedMemorySize, FWD_SMEM);
    cudaFuncSetAttribute(bwd_layer_k, cudaFuncAttributeMaxDynamicSharedMemorySize, BWD_SMEM);

    table_k<<<dim3(TABN,3),128>>>(filt_W1, filt_b1, filt_W2, filt_b2, p_tabW, p_tabD);
    edge_pre_k<<<(int)((ETOT+255)/256),256>>>(positions, idx_i, idx_j,
                                              p_d, p_fc, p_dfc, p_u, p_gd);
    gather_emb_k<<<(NATOMS*FDIM+255)/256,256>>>(emb, Z, p_x);

    for (int l = 0; l < NLAY; l++) {
        fwd_layer_k<<<NMOL,512,FWD_SMEM>>>(
            p_x, in2f_W + (size_t)l*FDIM*FDIM,
            f2_W1 + (size_t)l*FDIM*FDIM, f2_b1 + l*FDIM,
            f2_W2 + (size_t)l*FDIM*FDIM, f2_b2 + l*FDIM,
            p_tabW + (size_t)l*TABN*FDIM,
            p_fc, p_u,
            p_h + (size_t)l*NF, p_sig2 + (size_t)l*NF);
    }

    head_k<<<NMOL,256>>>(p_x, aw_W1, aw_b1, aw_W2, aw_b2,
                         out + (size_t)3*NATOMS, p_gx);

    for (int l = NLAY-1; l >= 0; l--) {
        bwd_layer_k<<<NMOL,512,BWD_SMEM>>>(
            p_gx, in2f_W + (size_t)l*FDIM*FDIM,
            f2_W1 + (size_t)l*FDIM*FDIM, f2_W2 + (size_t)l*FDIM*FDIM,
            p_sig2 + (size_t)l*NF, p_h + (size_t)l*NF,
            p_tabW + (size_t)l*TABN*FDIM, p_tabD + (size_t)l*TABN*FDIM,
            p_fc, p_dfc, p_u, p_gd);
    }

    action_k<<<NMOL,256>>>(positions, p_gd, p_d, idx_i, idx_j, out);
}

// round 5
// speedup vs baseline: 7.3164x; 1.0996x over previous
#include <cuda_runtime.h>
#include <math.h>

// ---------------- problem constants ----------------
#define NATOMS 16384
#define NMOL   512
#define APM    32
#define EPM    992
#define FDIM   128
#define NRBF   20
#define FH     64
#define NLAY   3
#define PI_F   3.14159265358979f
#define CUT    5.0f
#define LOG2_F 0.6931471805599453f
#define TABN   4096

static const size_t NF = (size_t)NATOMS * FDIM;

// ---------------- scratch ----------------
__device__ __align__(16) float  g_h    [3 * NF];
__device__ __align__(16) float  g_sig2 [3 * NF];
__device__ __align__(16) float  g_tabW [3 * TABN * FDIM];
__device__ __align__(16) float  g_tabD [3 * TABN * FDIM];
__device__ __align__(16) float2 g_tabWI[3 * TABN * FDIM];   // (value, slope)
__device__ __align__(16) float2 g_tabDI[3 * TABN * FDIM];

__device__ __forceinline__ float sspf(float v) {
    return fmaxf(v, 0.f) + log1pf(expf(-fabsf(v))) - LOG2_F;
}

// ---------------- filter table build ----------------
__global__ __launch_bounds__(128) void table_k(
    const float* __restrict__ W1, const float* __restrict__ b1,
    const float* __restrict__ W2, const float* __restrict__ b2,
    float* __restrict__ tabW, float* __restrict__ tabD)
{
    const int t = blockIdx.x;
    const int l = blockIdx.y;
    const int f = threadIdx.x;
    const float DELTA = CUT / (NRBF-1);
    const float CO = -0.5f / (DELTA*DELTA);
    const float d = t * (CUT / (TABN-1));

    __shared__ float rbf_s[NRBF], drbf_s[NRBF];
    __shared__ float t1_s[FDIM], dt1_s[FDIM];
    if (f < NRBF) {
        float u = d - f*DELTA;
        float g = expf(CO*u*u);
        rbf_s[f]  = g;
        drbf_s[f] = g * (2.f*CO*u);
    }
    __syncthreads();

    const float* W1l = W1 + (size_t)l*NRBF*FDIM;
    float p = b1[l*FDIM + f], dp = 0.f;
    #pragma unroll
    for (int k=0;k<NRBF;k++) {
        float w = W1l[k*FDIM + f];
        p  = fmaf(rbf_s[k],  w, p);
        dp = fmaf(drbf_s[k], w, dp);
    }
    float sg = 1.f/(1.f+expf(-p));
    t1_s[f]  = sspf(p);
    dt1_s[f] = sg*dp;
    __syncthreads();

    const float* W2l = W2 + (size_t)l*FDIM*FDIM;
    float w = b2[l*FDIM + f], dw = 0.f;
    #pragma unroll 8
    for (int c=0;c<FDIM;c++) {
        float wv = W2l[c*FDIM + f];
        w  = fmaf(t1_s[c],  wv, w);
        dw = fmaf(dt1_s[c], wv, dw);
    }
    size_t o = ((size_t)l*TABN + t)*FDIM + f;
    tabW[o] = w;
    tabD[o] = dw;
}

__global__ __launch_bounds__(128) void interleave_k(
    const float* __restrict__ tabW, const float* __restrict__ tabD,
    float2* __restrict__ tabWI, float2* __restrict__ tabDI)
{
    const int t = blockIdx.x, l = blockIdx.y, f = threadIdx.x;
    size_t o = ((size_t)l*TABN + t)*FDIM + f;
    float w0 = tabW[o];
    float w1 = (t < TABN-1) ? tabW[o + FDIM] : w0;
    tabWI[o] = make_float2(w0, w1 - w0);
    float d0 = tabD[o];
    float d1 = (t < TABN-1) ? tabD[o + FDIM] : d0;
    tabDI[o] = make_float2(d0, d1 - d0);
}

// ---------------- GEMM core: C(32x128) = A_s(atom-major) @ B ----------------
// TRANSB=false: B global [128][128] row-major. TRANSB=true: use B^T of [128][128].
template<bool TRANSB>
__device__ __forceinline__ void gemm128(const float* __restrict__ A_s,
                                        const float* __restrict__ Bg,
                                        float* Ws, int tid, int r0, int c0,
                                        float acc[2][4])
{
    #pragma unroll
    for (int m=0;m<2;m++)
        #pragma unroll
        for (int n=0;n<4;n++) acc[m][n] = 0.f;
    for (int k0=0;k0<FDIM;k0+=16) {
        __syncthreads();
        if (!TRANSB) {
            int row = tid>>5, c4 = (tid&31)<<2;
            *(float4*)&Ws[row*FDIM + c4] =
                *(const float4*)&Bg[(size_t)(k0+row)*FDIM + c4];
        } else {
            int c = tid>>2, kq = (tid&3)<<2;
            float4 w = *(const float4*)&Bg[(size_t)c*FDIM + k0 + kq];
            Ws[(kq+0)*FDIM + c] = w.x;
            Ws[(kq+1)*FDIM + c] = w.y;
            Ws[(kq+2)*FDIM + c] = w.z;
            Ws[(kq+3)*FDIM + c] = w.w;
        }
        __syncthreads();
        #pragma unroll
        for (int kk=0;kk<16;kk++) {
            float a0 = A_s[r0*FDIM + k0+kk];
            float a1 = A_s[(r0+1)*FDIM + k0+kk];
            float4 b = *(float4*)&Ws[kk*FDIM + c0];
            acc[0][0]=fmaf(a0,b.x,acc[0][0]); acc[0][1]=fmaf(a0,b.y,acc[0][1]);
            acc[0][2]=fmaf(a0,b.z,acc[0][2]); acc[0][3]=fmaf(a0,b.w,acc[0][3]);
            acc[1][0]=fmaf(a1,b.x,acc[1][0]); acc[1][1]=fmaf(a1,b.y,acc[1][1]);
            acc[1][2]=fmaf(a1,b.z,acc[1][2]); acc[1][3]=fmaf(a1,b.w,acc[1][3]);
        }
    }
}

// ---------------- the megakernel: one CTA per molecule ----------------
// smem pool layout (floats)
#define OFF_XS   0
#define OFF_HS   (OFF_XS + APM*FDIM)
#define OFF_AS   (OFF_HS + APM*FDIM)
#define OFF_TS   (OFF_AS + APM*FDIM)
#define OFF_WS   (OFF_TS + APM*FDIM)
#define OFF_FU   (OFF_WS + 16*FDIM)          // float2[EPM]
#define OFF_GD   (OFF_FU + 2*EPM)
#define OFF_POS  (OFF_GD + EPM)
#define OFF_ES   (OFF_POS + 96)
#define SM_FLOATS (OFF_ES + 32)

__global__ __launch_bounds__(512,2) void mega_k(
    const float* __restrict__ pos, const float* __restrict__ emb,
    const int* __restrict__ Z,
    const float* __restrict__ in2f_W,
    const float* __restrict__ f2_W1, const float* __restrict__ f2_b1,
    const float* __restrict__ f2_W2, const float* __restrict__ f2_b2,
    const float* __restrict__ aw_W1, const float* __restrict__ aw_b1,
    const float* __restrict__ aw_W2, const float* __restrict__ aw_b2,
    const float2* __restrict__ tabWI, const float2* __restrict__ tabDI,
    float* __restrict__ g_h_, float* __restrict__ g_sig2_,
    float* __restrict__ out)
{
    extern __shared__ float sm[];
    float*  Xs    = sm + OFF_XS;
    float*  Hs    = sm + OFF_HS;
    float*  As    = sm + OFF_AS;
    float*  Ts    = sm + OFF_TS;
    float*  Ws    = sm + OFF_WS;
    float2* fu    = (float2*)(sm + OFF_FU);
    float*  gd_s  = sm + OFF_GD;
    float*  pos_s = sm + OFF_POS;
    float*  es    = sm + OFF_ES;

    const int tid = threadIdx.x;
    const int mol = blockIdx.x;
    const int abase = mol*APM;

    const int rg = tid>>5, cg = tid&31;
    const int r0 = rg<<1, c0 = cg<<2;
    const int f2 = tid & 63, er = tid >> 6;     // edge-loop mapping

    // ---------- P0: load pos, gather x, zero gd ----------
    if (tid < 96) pos_s[tid] = pos[abase*3 + tid];
    for (int t=tid; t<APM*FDIM/4; t+=512) {
        int a = t>>5, f4 = (t&31)<<2;
        int z = Z[abase + a];
        *(float4*)&Xs[a*FDIM + f4] = *(const float4*)&emb[(size_t)z*FDIM + f4];
    }
    for (int t=tid; t<EPM; t+=512) gd_s[t] = 0.f;
    __syncthreads();

    // ---------- P0b: per-edge fc, u ----------
    for (int el=tid; el<EPM; el+=512) {
        int i = el/31, c = el - i*31;
        int j = c + (c>=i ? 1 : 0);
        float rx = pos_s[j*3+0]-pos_s[i*3+0];
        float ry = pos_s[j*3+1]-pos_s[i*3+1];
        float rz = pos_s[j*3+2]-pos_s[i*3+2];
        float d = sqrtf(rx*rx+ry*ry+rz*rz + 1e-12f);
        float fcv = 0.f, uv = 0.f;
        if (d < CUT) {
            fcv = 0.5f*(cosf(PI_F*d/CUT)+1.f);
            uv = fminf(d*((float)(TABN-1)/CUT), (float)(TABN-2)+0.9999f);
        }
        fu[el] = make_float2(fcv, uv);
    }
    // (gemm128's leading __syncthreads makes fu/Xs visible before use)

    // =============== forward layers ===============
    for (int l = 0; l < NLAY; l++) {
        const float* W0 = in2f_W + (size_t)l*FDIM*FDIM;
        const float* W1 = f2_W1  + (size_t)l*FDIM*FDIM;
        const float* W2 = f2_W2  + (size_t)l*FDIM*FDIM;
        const float2* tWI = tabWI + (size_t)l*TABN*FDIM;
        float* h_g = g_h_ + (size_t)l*NF;
        float* s_g = g_sig2_ + (size_t)l*NF;

        float acc[2][4];
        // GEMM1: h = x @ W0
        gemm128<false>(Xs, W0, Ws, tid, r0, c0, acc);
        #pragma unroll
        for (int m=0;m<2;m++) {
            float4 v = make_float4(acc[m][0],acc[m][1],acc[m][2],acc[m][3]);
            *(float4*)&Hs[(r0+m)*FDIM + c0] = v;
            *(float4*)&h_g[(size_t)(abase+r0+m)*FDIM + c0] = v;
        }
        __syncthreads();

        // agg: As[i][f] = sum_j h[j][f]*fc*Wf(d)
        for (int it=0; it<4; it++) {
            int i = it*8 + er;
            float ax=0.f, ay=0.f;
            const int eb = i*31;
            for (int c=0;c<31;c++) {
                float2 fuv = fu[eb+c];
                if (fuv.x != 0.f) {
                    int j = (c<i) ? c : c+1;
                    int t0 = (int)fuv.y; float fr = fuv.y - (float)t0;
                    float4 wv = *(const float4*)&tWI[(size_t)t0*FDIM + 2*f2];
                    float wx = fmaf(fr, wv.y, wv.x);
                    float wy = fmaf(fr, wv.w, wv.z);
                    float2 hv = *(const float2*)&Hs[j*FDIM + 2*f2];
                    ax = fmaf(hv.x*fuv.x, wx, ax);
                    ay = fmaf(hv.y*fuv.x, wy, ay);
                }
            }
            *(float2*)&As[i*FDIM + 2*f2] = make_float2(ax, ay);
        }

        // GEMM2: pre = agg@W1 + b1; sig2 -> global; t2=ssp -> Ts
        gemm128<false>(As, W1, Ws, tid, r0, c0, acc);
        {
            float4 b1v = *(const float4*)&f2_b1[l*FDIM + c0];
            float bb[4]={b1v.x,b1v.y,b1v.z,b1v.w};
            #pragma unroll
            for (int m=0;m<2;m++) {
                float sg4[4];
                #pragma unroll
                for (int n=0;n<4;n++) {
                    float pre = acc[m][n] + bb[n];
                    sg4[n] = 1.f/(1.f+expf(-pre));
                    Ts[(r0+m)*FDIM + c0 + n] = sspf(pre);
                }
                *(float4*)&s_g[(size_t)(abase+r0+m)*FDIM + c0] =
                    make_float4(sg4[0],sg4[1],sg4[2],sg4[3]);
            }
        }

        // GEMM3: x += t2@W2 + b2
        gemm128<false>(Ts, W2, Ws, tid, r0, c0, acc);
        {
            float4 b2v = *(const float4*)&f2_b2[l*FDIM + c0];
            #pragma unroll
            for (int m=0;m<2;m++) {
                float* xp = &Xs[(r0+m)*FDIM + c0];
                xp[0] += acc[m][0] + b2v.x;
                xp[1] += acc[m][1] + b2v.y;
                xp[2] += acc[m][2] + b2v.z;
                xp[3] += acc[m][3] + b2v.w;
            }
        }
        __syncthreads();
    }

    // =============== head: fwd + bwd ===============
    {
        if (tid < APM) es[tid] = 0.f;
        // GEMMh: pre = x @ aw_W1 (128->64) + b1
        const int hc0 = cg<<1;   // 2 cols per thread
        float acc[2][2] = {};
        for (int k0=0;k0<FDIM;k0+=16) {
            __syncthreads();
            if (tid < 256) {
                int row = tid>>4, c4 = (tid&15)<<2;
                *(float4*)&Ws[row*FH + c4] =
                    *(const float4*)&aw_W1[(size_t)(k0+row)*FH + c4];
            }
            __syncthreads();
            #pragma unroll
            for (int kk=0;kk<16;kk++) {
                float a0 = Xs[r0*FDIM + k0+kk];
                float a1 = Xs[(r0+1)*FDIM + k0+kk];
                float2 b = *(float2*)&Ws[kk*FH + hc0];
                acc[0][0]=fmaf(a0,b.x,acc[0][0]); acc[0][1]=fmaf(a0,b.y,acc[0][1]);
                acc[1][0]=fmaf(a1,b.x,acc[1][0]); acc[1][1]=fmaf(a1,b.y,acc[1][1]);
            }
        }
        float2 b1v = *(const float2*)&aw_b1[hc0];
        float2 w2v = *(const float2*)&aw_W2[hc0];
        float ep[2];
        #pragma unroll
        for (int m=0;m<2;m++) {
            float pre0 = acc[m][0] + b1v.x;
            float pre1 = acc[m][1] + b1v.y;
            float sg0 = 1.f/(1.f+expf(-pre0));
            float sg1 = 1.f/(1.f+expf(-pre1));
            ep[m] = sspf(pre0)*w2v.x + sspf(pre1)*w2v.y;
            Ts[(r0+m)*FH + hc0 + 0] = sg0*w2v.x;
            Ts[(r0+m)*FH + hc0 + 1] = sg1*w2v.y;
        }
        // warp-reduce energy partials (each warp owns rows r0, r0+1)
        #pragma unroll
        for (int o=16;o>0;o>>=1) {
            ep[0] += __shfl_xor_sync(0xffffffffu, ep[0], o);
            ep[1] += __shfl_xor_sync(0xffffffffu, ep[1], o);
        }
        if (cg == 0) { es[r0] = ep[0]; es[r0+1] = ep[1]; }
        __syncthreads();
        if (tid == 0) {
            float s = APM * aw_b2[0];
            #pragma unroll
            for (int a=0;a<APM;a++) s += es[a];
            out[(size_t)3*NATOMS + mol] = s;
        }
        // GEMM2h: gx = gp @ aw_W1^T (64->128) -> Xs
        float acc2[2][4] = {};
        for (int k0=0;k0<FH;k0+=16) {
            __syncthreads();
            {
                int f = tid>>2, kq = (tid&3)<<2;
                float4 w = *(const float4*)&aw_W1[(size_t)f*FH + k0 + kq];
                Ws[(kq+0)*FDIM + f] = w.x;
                Ws[(kq+1)*FDIM + f] = w.y;
                Ws[(kq+2)*FDIM + f] = w.z;
                Ws[(kq+3)*FDIM + f] = w.w;
            }
            __syncthreads();
            #pragma unroll
            for (int kk=0;kk<16;kk++) {
                float a0 = Ts[r0*FH + k0+kk];
                float a1 = Ts[(r0+1)*FH + k0+kk];
                float4 b = *(float4*)&Ws[kk*FDIM + c0];
                acc2[0][0]=fmaf(a0,b.x,acc2[0][0]); acc2[0][1]=fmaf(a0,b.y,acc2[0][1]);
                acc2[0][2]=fmaf(a0,b.z,acc2[0][2]); acc2[0][3]=fmaf(a0,b.w,acc2[0][3]);
                acc2[1][0]=fmaf(a1,b.x,acc2[1][0]); acc2[1][1]=fmaf(a1,b.y,acc2[1][1]);
                acc2[1][2]=fmaf(a1,b.z,acc2[1][2]); acc2[1][3]=fmaf(a1,b.w,acc2[1][3]);
            }
        }
        __syncthreads();   // all reads of Xs (GEMMh) done before overwrite
        #pragma unroll
        for (int m=0;m<2;m++)
            *(float4*)&Xs[(r0+m)*FDIM + c0] =
                make_float4(acc2[m][0],acc2[m][1],acc2[m][2],acc2[m][3]);
        __syncthreads();
    }

    // =============== backward layers ===============
    for (int l = NLAY-1; l >= 0; l--) {
        const float* W0 = in2f_W + (size_t)l*FDIM*FDIM;
        const float* W1 = f2_W1  + (size_t)l*FDIM*FDIM;
        const float* W2 = f2_W2  + (size_t)l*FDIM*FDIM;
        const float2* tWI = tabWI + (size_t)l*TABN*FDIM;
        const float2* tDI = tabDI + (size_t)l*TABN*FDIM;
        const float* h_g = g_h_ + (size_t)l*NF;
        const float* s_g = g_sig2_ + (size_t)l*NF;

        // reload h (previous layer's readers of Hs passed a barrier already)
        for (int t=tid; t<APM*FDIM/4; t+=512) {
            int a = t>>5, f4 = (t&31)<<2;
            *(float4*)&Hs[a*FDIM + f4] =
                *(const float4*)&h_g[(size_t)(abase+a)*FDIM + f4];
        }

        float acc[2][4];
        // GEMM1: gpre2 = (gx @ W2^T) * sig2 -> Ts
        gemm128<true>(Xs, W2, Ws, tid, r0, c0, acc);
        #pragma unroll
        for (int m=0;m<2;m++) {
            float4 s4 = *(const float4*)&s_g[(size_t)(abase+r0+m)*FDIM + c0];
            Ts[(r0+m)*FDIM + c0 + 0] = acc[m][0]*s4.x;
            Ts[(r0+m)*FDIM + c0 + 1] = acc[m][1]*s4.y;
            Ts[(r0+m)*FDIM + c0 + 2] = acc[m][2]*s4.z;
            Ts[(r0+m)*FDIM + c0 + 3] = acc[m][3]*s4.w;
        }

        // GEMM2: ga = gpre2 @ W1^T -> As
        gemm128<true>(Ts, W1, Ws, tid, r0, c0, acc);
        #pragma unroll
        for (int m=0;m<2;m++)
            *(float4*)&As[(r0+m)*FDIM + c0] =
                make_float4(acc[m][0],acc[m][1],acc[m][2],acc[m][3]);
        __syncthreads();

        // gh phase: Ts[j][f] = sum_i ga[i][f]*fc*W
        for (int jt=0; jt<4; jt++) {
            int j = jt*8 + er;
            float ghx=0.f, ghy=0.f;
            for (int i=0;i<APM;i++) {
                if (i == j) continue;
                int el = i*31 + ((j<i)? j : j-1);
                float2 fuv = fu[el];
                if (fuv.x != 0.f) {
                    int t0 = (int)fuv.y; float fr = fuv.y - (float)t0;
                    float4 wv = *(const float4*)&tWI[(size_t)t0*FDIM + 2*f2];
                    float wx = fmaf(fr, wv.y, wv.x);
                    float wy = fmaf(fr, wv.w, wv.z);
                    float2 ga = *(const float2*)&As[i*FDIM + 2*f2];
                    ghx = fmaf(ga.x*fuv.x, wx, ghx);
                    ghy = fmaf(ga.y*fuv.x, wy, ghy);
                }
            }
            *(float2*)&Ts[j*FDIM + 2*f2] = make_float2(ghx, ghy);
        }

        // gd phase: warp-per-edge
        {
            const int warp = tid >> 5, lane = cg;
            for (int el = warp; el < EPM; el += 16) {
                float2 fuv = fu[el];
                if (fuv.x == 0.f) continue;
                int i = el/31, c = el - i*31;
                int j = c + (c>=i ? 1 : 0);
                int t0 = (int)fuv.y; float fr = fuv.y - (float)t0;
                float cs = 2.f*fuv.x - 1.f;
                float dfc = -(0.5f*PI_F/CUT) * sqrtf(fmaxf(1.f - cs*cs, 0.f));
                float sW = 0.f, sD = 0.f;
                #pragma unroll
                for (int hh=0; hh<2; hh++) {
                    int f0 = hh*64 + 2*lane;
                    float4 wv = *(const float4*)&tWI[(size_t)t0*FDIM + f0];
                    float4 dv = *(const float4*)&tDI[(size_t)t0*FDIM + f0];
                    float2 ga = *(const float2*)&As[i*FDIM + f0];
                    float2 hv = *(const float2*)&Hs[j*FDIM + f0];
                    float p0 = ga.x*hv.x, p1 = ga.y*hv.y;
                    sW += p0*fmaf(fr,wv.y,wv.x) + p1*fmaf(fr,wv.w,wv.z);
                    sD += p0*fmaf(fr,dv.y,dv.x) + p1*fmaf(fr,dv.w,dv.z);
                }
                float term = fmaf(fuv.x, sD, dfc*sW);
                #pragma unroll
                for (int o=16;o>0;o>>=1) term += __shfl_xor_sync(0xffffffffu, term, o);
                if (lane == 0) gd_s[el] += term;
            }
        }

        // GEMM3: gx += gh @ W0^T
        gemm128<true>(Ts, W0, Ws, tid, r0, c0, acc);
        #pragma unroll
        for (int m=0;m<2;m++) {
            float* gp = &Xs[(r0+m)*FDIM + c0];
            gp[0] += acc[m][0]; gp[1] += acc[m][1];
            gp[2] += acc[m][2]; gp[3] += acc[m][3];
        }
        __syncthreads();
    }

    // =============== action: grad_pos, clip, write ===============
    {
        float* gp  = Ws;          // 96
        float* nrm = Ws + 96;     // 32
        float* cf  = Ws + 128;    // 1
        if (tid < 96) gp[tid] = 0.f;
        __syncthreads();
        for (int el=tid; el<EPM; el+=512) {
            float g = gd_s[el];
            if (g != 0.f) {
                int i = el/31, c = el - i*31;
                int j = c + (c>=i ? 1 : 0);
                float rx = pos_s[j*3+0]-pos_s[i*3+0];
                float ry = pos_s[j*3+1]-pos_s[i*3+1];
                float rz = pos_s[j*3+2]-pos_s[i*3+2];
                float d = sqrtf(rx*rx+ry*ry+rz*rz + 1e-12f);
                g /= d;
                atomicAdd(&gp[j*3+0],  g*rx); atomicAdd(&gp[j*3+1],  g*ry);
                atomicAdd(&gp[j*3+2],  g*rz);
                atomicAdd(&gp[i*3+0], -g*rx); atomicAdd(&gp[i*3+1], -g*ry);
                atomicAdd(&gp[i*3+2], -g*rz);
            }
        }
        __syncthreads();
        if (tid < APM) {
            float ax = gp[tid*3+0], ay = gp[tid*3+1], az = gp[tid*3+2];
            nrm[tid] = sqrtf(ax*ax + ay*ay + az*az);
        }
        __syncthreads();
        if (tid == 0) {
            float mx = 0.f;
            #pragma unroll
            for (int a=0;a<APM;a++) mx = fmaxf(mx, nrm[a]);
            cf[0] = fminf(1.0f / fmaxf(mx, 1e-8f), 1.0f);
        }
        __syncthreads();
        float coef = cf[0];
        for (int t=tid; t<96; t+=512)
            out[(size_t)abase*3 + t] = -gp[t]*coef;
    }
}

// ---------------- host ----------------
static const int MEGA_SMEM = SM_FLOATS * 4;

extern "C" void kernel_launch(void* const* d_in, const int* in_sizes, int n_in,
                              void* d_out, int out_size)
{
    const float* positions = (const float*)d_in[0];
    const float* emb       = (const float*)d_in[1];
    const float* in2f_W    = (const float*)d_in[2];
    const float* filt_W1   = (const float*)d_in[3];
    const float* filt_b1   = (const float*)d_in[4];
    const float* filt_W2   = (const float*)d_in[5];
    const float* filt_b2   = (const float*)d_in[6];
    const float* f2_W1     = (const float*)d_in[7];
    const float* f2_b1     = (const float*)d_in[8];
    const float* f2_W2     = (const float*)d_in[9];
    const float* f2_b2     = (const float*)d_in[10];
    const float* aw_W1     = (const float*)d_in[11];
    const float* aw_b1     = (const float*)d_in[12];
    const float* aw_W2     = (const float*)d_in[13];
    const float* aw_b2     = (const float*)d_in[14];
    const int*   Z         = (const int*)d_in[15];
    float* out = (float*)d_out;

    float *p_h, *p_sig2, *p_tabW, *p_tabD;
    float2 *p_tabWI, *p_tabDI;
    cudaGetSymbolAddress((void**)&p_h,     g_h);
    cudaGetSymbolAddress((void**)&p_sig2,  g_sig2);
    cudaGetSymbolAddress((void**)&p_tabW,  g_tabW);
    cudaGetSymbolAddress((void**)&p_tabD,  g_tabD);
    cudaGetSymbolAddress((void**)&p_tabWI, g_tabWI);
    cudaGetSymbolAddress((void**)&p_tabDI, g_tabDI);

    cudaFuncSetAttribute(mega_k, cudaFuncAttributeMaxDynamicSharedMemorySize,
                         MEGA_SMEM);

    table_k<<<dim3(TABN,3),128>>>(filt_W1, filt_b1, filt_W2, filt_b2,
                                  p_tabW, p_tabD);
    interleave_k<<<dim3(TABN,3),128>>>(p_tabW, p_tabD, p_tabWI, p_tabDI);
    mega_k<<<NMOL, 512, MEGA_SMEM>>>(
        positions, emb, Z, in2f_W,
        f2_W1, f2_b1, f2_W2, f2_b2,
        aw_W1, aw_b1, aw_W2, aw_b2,
        p_tabWI, p_tabDI, p_h, p_sig2, out);
}

// round 6
// speedup vs baseline: 8.7301x; 1.1932x over previous
#include <cuda_runtime.h>
#include <math.h>

// ---------------- problem constants ----------------
#define NATOMS 16384
#define NMOL   512
#define APM    32
#define FDIM   128
#define NRBF   20
#define FH     64
#define NLAY   3
#define PI_F   3.14159265358979f
#define CUT    5.0f
#define LOG2_F 0.6931471805599453f
#define TABN   1024

static const size_t NF = (size_t)NATOMS * FDIM;

typedef unsigned long long ull;

// ---------------- scratch ----------------
__device__ __align__(16) float  g_h    [2 * NF];               // layers 0,1 only
__device__ __align__(16) float  g_sig2 [3 * NF];
__device__ __align__(16) float  g_tabW [3 * TABN * FDIM];
__device__ __align__(16) float  g_tabD [3 * TABN * FDIM];
__device__ __align__(16) float4 g_tabW4[3 * TABN * 64];        // (v0,v1,s0,s1) per feature pair
__device__ __align__(16) float4 g_tabD4[3 * TABN * 64];

__device__ __forceinline__ float sspf(float v) {
    return fmaxf(v, 0.f) + log1pf(expf(-fabsf(v))) - LOG2_F;
}
__device__ __forceinline__ ull pk2(float x) {
    ull r; asm("mov.b64 %0, {%1, %1};" : "=l"(r) : "f"(x)); return r;
}
__device__ __forceinline__ ull fma2(ull a, ull b, ull c) {
    ull d; asm("fma.rn.f32x2 %0, %1, %2, %3;" : "=l"(d) : "l"(a), "l"(b), "l"(c)); return d;
}
__device__ __forceinline__ ull mul2(ull a, ull b) {
    ull d; asm("mul.rn.f32x2 %0, %1, %2;" : "=l"(d) : "l"(a), "l"(b)); return d;
}
__device__ __forceinline__ float2 upk(ull v) {
    float2 r; asm("mov.b64 {%0, %1}, %2;" : "=f"(r.x), "=f"(r.y) : "l"(v)); return r;
}

// ---------------- filter table build ----------------
__global__ __launch_bounds__(128) void table_k(
    const float* __restrict__ W1, const float* __restrict__ b1,
    const float* __restrict__ W2, const float* __restrict__ b2,
    float* __restrict__ tabW, float* __restrict__ tabD)
{
    const int t = blockIdx.x;
    const int l = blockIdx.y;
    const int f = threadIdx.x;
    const float DELTA = CUT / (NRBF-1);
    const float CO = -0.5f / (DELTA*DELTA);
    const float d = t * (CUT / (TABN-1));

    __shared__ float rbf_s[NRBF], drbf_s[NRBF];
    __shared__ float t1_s[FDIM], dt1_s[FDIM];
    if (f < NRBF) {
        float u = d - f*DELTA;
        float g = expf(CO*u*u);
        rbf_s[f]  = g;
        drbf_s[f] = g * (2.f*CO*u);
    }
    __syncthreads();

    const float* W1l = W1 + (size_t)l*NRBF*FDIM;
    float p = b1[l*FDIM + f], dp = 0.f;
    #pragma unroll
    for (int k=0;k<NRBF;k++) {
        float w = W1l[k*FDIM + f];
        p  = fmaf(rbf_s[k],  w, p);
        dp = fmaf(drbf_s[k], w, dp);
    }
    float sg = 1.f/(1.f+expf(-p));
    t1_s[f]  = sspf(p);
    dt1_s[f] = sg*dp;
    __syncthreads();

    const float* W2l = W2 + (size_t)l*FDIM*FDIM;
    float w = b2[l*FDIM + f], dw = 0.f;
    #pragma unroll 8
    for (int c=0;c<FDIM;c++) {
        float wv = W2l[c*FDIM + f];
        w  = fmaf(t1_s[c],  wv, w);
        dw = fmaf(dt1_s[c], wv, dw);
    }
    size_t o = ((size_t)l*TABN + t)*FDIM + f;
    tabW[o] = w;
    tabD[o] = dw;
}

// interleave into feature-pair records: (v0, v1, slope0, slope1)
__global__ __launch_bounds__(64) void interleave4_k(
    const float* __restrict__ tabW, const float* __restrict__ tabD,
    float4* __restrict__ tabW4, float4* __restrict__ tabD4)
{
    const int t = blockIdx.x, l = blockIdx.y, f = threadIdx.x; // f = pair index 0..63
    size_t o = ((size_t)l*TABN + t)*FDIM;
    size_t o4 = ((size_t)l*TABN + t)*64 + f;
    float v0 = tabW[o + 2*f], v1 = tabW[o + 2*f + 1];
    float n0 = (t < TABN-1) ? tabW[o + FDIM + 2*f]     : v0;
    float n1 = (t < TABN-1) ? tabW[o + FDIM + 2*f + 1] : v1;
    tabW4[o4] = make_float4(v0, v1, n0 - v0, n1 - v1);
    float d0 = tabD[o + 2*f], d1 = tabD[o + 2*f + 1];
    float m0 = (t < TABN-1) ? tabD[o + FDIM + 2*f]     : d0;
    float m1 = (t < TABN-1) ? tabD[o + FDIM + 2*f + 1] : d1;
    tabD4[o4] = make_float4(d0, d1, m0 - d0, m1 - d1);
}

// ---------------- GEMM: C(32x128) = A_s @ B, f32x2 + double-buffered weights ----
template<bool TRANSB>
__device__ __forceinline__ void ldW(float* Wd, const float* __restrict__ Bg,
                                    int k0, int tid)
{
    if (!TRANSB) {
        int row = tid>>5, c4 = (tid&31)<<2;
        *(float4*)&Wd[row*FDIM + c4] =
            *(const float4*)&Bg[(size_t)(k0+row)*FDIM + c4];
    } else {
        int c = tid>>2, kq = (tid&3)<<2;
        float4 w = *(const float4*)&Bg[(size_t)c*FDIM + k0 + kq];
        Wd[(kq+0)*FDIM + c] = w.x;
        Wd[(kq+1)*FDIM + c] = w.y;
        Wd[(kq+2)*FDIM + c] = w.z;
        Wd[(kq+3)*FDIM + c] = w.w;
    }
}

template<bool TRANSB>
__device__ __forceinline__ void gemm128(const float* __restrict__ A_s,
                                        const float* __restrict__ Bg,
                                        float* Ws, int tid, int r0, int c0,
                                        float out[2][4])
{
    ull acc00=0ull, acc01=0ull, acc10=0ull, acc11=0ull;
    ldW<TRANSB>(Ws, Bg, 0, tid);
    __syncthreads();
    for (int ch=0; ch<8; ch++) {
        const float* Wc = Ws + (ch&1)*2048;
        if (ch < 7) ldW<TRANSB>(Ws + ((ch+1)&1)*2048, Bg, (ch+1)*16, tid);
        const int k0 = ch*16;
        #pragma unroll
        for (int kk=0;kk<16;kk++) {
            ull a0p = pk2(A_s[r0*FDIM + k0+kk]);
            ull a1p = pk2(A_s[(r0+1)*FDIM + k0+kk]);
            ulonglong2 bp = *(const ulonglong2*)&Wc[kk*FDIM + c0];
            acc00 = fma2(a0p, bp.x, acc00);
            acc01 = fma2(a0p, bp.y, acc01);
            acc10 = fma2(a1p, bp.x, acc10);
            acc11 = fma2(a1p, bp.y, acc11);
        }
        __syncthreads();
    }
    float2 v;
    v = upk(acc00); out[0][0]=v.x; out[0][1]=v.y;
    v = upk(acc01); out[0][2]=v.x; out[0][3]=v.y;
    v = upk(acc10); out[1][0]=v.x; out[1][1]=v.y;
    v = upk(acc11); out[1][2]=v.x; out[1][3]=v.y;
}

// ---------------- smem pool (floats) ----------------
#define OFF_XS   0
#define OFF_HS   (OFF_XS + APM*FDIM)
#define OFF_AS   (OFF_HS + APM*FDIM)
#define OFF_TS   (OFF_AS + APM*FDIM)
#define OFF_WS   (OFF_TS + APM*FDIM)        // 2 x 2048
#define OFF_LI   (OFF_WS + 4096)            // float2[APM*31]
#define OFF_LJ   (OFF_LI + 2*APM*31)
#define OFF_GD   (OFF_LJ + 2*APM*31)        // float[APM*31]
#define OFF_POS  (OFF_GD + APM*31)
#define OFF_CNT  (OFF_POS + 96)             // int[64]
#define OFF_ES   (OFF_CNT + 64)
#define SM_FLOATS (OFF_ES + 32)

__global__ __launch_bounds__(512,2) void mega_k(
    const float* __restrict__ pos, const float* __restrict__ emb,
    const int* __restrict__ Z,
    const float* __restrict__ in2f_W,
    const float* __restrict__ f2_W1, const float* __restrict__ f2_b1,
    const float* __restrict__ f2_W2, const float* __restrict__ f2_b2,
    const float* __restrict__ aw_W1, const float* __restrict__ aw_b1,
    const float* __restrict__ aw_W2, const float* __restrict__ aw_b2,
    const float4* __restrict__ tabW4g, const float4* __restrict__ tabD4g,
    float* __restrict__ g_h_, float* __restrict__ g_sig2_,
    float* __restrict__ out)
{
    extern __shared__ float sm[];
    float*  Xs    = sm + OFF_XS;
    float*  Hs    = sm + OFF_HS;
    float*  As    = sm + OFF_AS;
    float*  Ts    = sm + OFF_TS;
    float*  Ws    = sm + OFF_WS;
    float2* liI   = (float2*)(sm + OFF_LI);
    float2* liJ   = (float2*)(sm + OFF_LJ);
    float*  gd_s  = sm + OFF_GD;
    float*  pos_s = sm + OFF_POS;
    int*    cntI  = (int*)(sm + OFF_CNT);
    int*    cntJ  = cntI + 32;
    float*  es    = sm + OFF_ES;

    const int tid = threadIdx.x;
    const int mol = blockIdx.x;
    const int abase = mol*APM;

    const int rg = tid>>5, cg = tid&31;
    const int r0 = rg<<1, c0 = cg<<2;
    const int f2 = tid & 63, er = tid >> 6;

    // ---------- P0: pos, gather x, zero gd ----------
    if (tid < 96) pos_s[tid] = pos[abase*3 + tid];
    for (int t=tid; t<APM*FDIM/4; t+=512) {
        int a = t>>5, f4 = (t&31)<<2;
        int z = Z[abase + a];
        *(float4*)&Xs[a*FDIM + f4] = *(const float4*)&emb[(size_t)z*FDIM + f4];
    }
    for (int t=tid; t<APM*31; t+=512) gd_s[t] = 0.f;
    __syncthreads();

    // ---------- P0b: build compacted edge lists (deterministic) ----------
    if (tid < 64) {
        const int role = tid >> 5;      // 0: by-i list, 1: by-j list
        const int a = tid & 31;
        int count = 0;
        for (int c=0; c<31; c++) {
            int other = c + (c >= a ? 1 : 0);
            int i = role==0 ? a : other;
            int j = role==0 ? other : a;
            float rx = pos_s[j*3+0]-pos_s[i*3+0];
            float ry = pos_s[j*3+1]-pos_s[i*3+1];
            float rz = pos_s[j*3+2]-pos_s[i*3+2];
            float d = sqrtf(rx*rx+ry*ry+rz*rz + 1e-12f);
            if (d < CUT) {
                float fc = 0.5f*(cosf(PI_F*d*(1.f/CUT))+1.f);
                float u = fminf(fmaxf(d*((float)(TABN-1)/CUT), 0.01f),
                                (float)(TABN-2) + 0.999f);
                float enc = (float)(role==0 ? j : i)*2048.f + u;
                if (role==0) liI[a*31+count] = make_float2(fc, enc);
                else         liJ[a*31+count] = make_float2(fc, enc);
                count++;
            }
        }
        if (role==0) cntI[a] = count; else cntJ[a] = count;
    }
    __syncthreads();

    // =============== forward layers ===============
    for (int l = 0; l < NLAY; l++) {
        const float* W0 = in2f_W + (size_t)l*FDIM*FDIM;
        const float* W1 = f2_W1  + (size_t)l*FDIM*FDIM;
        const float* W2 = f2_W2  + (size_t)l*FDIM*FDIM;
        const float4* tW4 = tabW4g + (size_t)l*TABN*64;
        float* s_g = g_sig2_ + (size_t)l*NF;

        float acc[2][4];
        // GEMM1: h = x @ W0
        gemm128<false>(Xs, W0, Ws, tid, r0, c0, acc);
        #pragma unroll
        for (int m=0;m<2;m++) {
            float4 v = make_float4(acc[m][0],acc[m][1],acc[m][2],acc[m][3]);
            *(float4*)&Hs[(r0+m)*FDIM + c0] = v;
            if (l < 2)
                *(float4*)&g_h_[(size_t)l*NF + (size_t)(abase+r0+m)*FDIM + c0] = v;
        }
        __syncthreads();

        // agg: As[i][f-pair] via compacted listI
        for (int it=0; it<4; it++) {
            int i = it*8 + er;
            int cnt = cntI[i];
            ull accp = 0ull;
            for (int c=0;c<cnt;c++) {
                float2 e = liI[i*31+c];
                float enc = e.y;
                int j = (int)(enc * (1.f/2048.f));
                float u = enc - (float)j*2048.f;
                int t0 = (int)u;
                float fr = u - (float)t0;
                ulonglong2 wv = *(const ulonglong2*)&tW4[((size_t)t0<<6) + f2];
                ull w01 = fma2(pk2(fr), wv.y, wv.x);
                ull h01 = *(const ull*)&Hs[j*FDIM + 2*f2];
                accp = fma2(mul2(h01, pk2(e.x)), w01, accp);
            }
            *(ull*)&As[i*FDIM + 2*f2] = accp;
        }

        // GEMM2: pre = agg@W1 + b1; sig2->global; t2=ssp->Ts
        gemm128<false>(As, W1, Ws, tid, r0, c0, acc);
        {
            float4 b1v = *(const float4*)&f2_b1[l*FDIM + c0];
            float bb[4]={b1v.x,b1v.y,b1v.z,b1v.w};
            #pragma unroll
            for (int m=0;m<2;m++) {
                float sg4[4];
                #pragma unroll
                for (int n=0;n<4;n++) {
                    float pre = acc[m][n] + bb[n];
                    sg4[n] = 1.f/(1.f+expf(-pre));
                    Ts[(r0+m)*FDIM + c0 + n] = sspf(pre);
                }
                *(float4*)&s_g[(size_t)(abase+r0+m)*FDIM + c0] =
                    make_float4(sg4[0],sg4[1],sg4[2],sg4[3]);
            }
        }

        // GEMM3: x += t2@W2 + b2
        gemm128<false>(Ts, W2, Ws, tid, r0, c0, acc);
        {
            float4 b2v = *(const float4*)&f2_b2[l*FDIM + c0];
            #pragma unroll
            for (int m=0;m<2;m++) {
                float* xp = &Xs[(r0+m)*FDIM + c0];
                xp[0] += acc[m][0] + b2v.x;
                xp[1] += acc[m][1] + b2v.y;
                xp[2] += acc[m][2] + b2v.z;
                xp[3] += acc[m][3] + b2v.w;
            }
        }
    }

    // =============== head: fwd + bwd ===============
    {
        if (tid < APM) es[tid] = 0.f;
        const int hc0 = cg<<1;
        float acc[2][2] = {};
        for (int k0=0;k0<FDIM;k0+=16) {
            __syncthreads();
            if (tid < 256) {
                int row = tid>>4, c4 = (tid&15)<<2;
                *(float4*)&Ws[row*FH + c4] =
                    *(const float4*)&aw_W1[(size_t)(k0+row)*FH + c4];
            }
            __syncthreads();
            #pragma unroll
            for (int kk=0;kk<16;kk++) {
                float a0 = Xs[r0*FDIM + k0+kk];
                float a1 = Xs[(r0+1)*FDIM + k0+kk];
                float2 b = *(float2*)&Ws[kk*FH + hc0];
                acc[0][0]=fmaf(a0,b.x,acc[0][0]); acc[0][1]=fmaf(a0,b.y,acc[0][1]);
                acc[1][0]=fmaf(a1,b.x,acc[1][0]); acc[1][1]=fmaf(a1,b.y,acc[1][1]);
            }
        }
        float2 b1v = *(const float2*)&aw_b1[hc0];
        float2 w2v = *(const float2*)&aw_W2[hc0];
        float ep[2];
        #pragma unroll
        for (int m=0;m<2;m++) {
            float pre0 = acc[m][0] + b1v.x;
            float pre1 = acc[m][1] + b1v.y;
            float sg0 = 1.f/(1.f+expf(-pre0));
            float sg1 = 1.f/(1.f+expf(-pre1));
            ep[m] = sspf(pre0)*w2v.x + sspf(pre1)*w2v.y;
            Ts[(r0+m)*FH + hc0 + 0] = sg0*w2v.x;
            Ts[(r0+m)*FH + hc0 + 1] = sg1*w2v.y;
        }
        #pragma unroll
        for (int o=16;o>0;o>>=1) {
            ep[0] += __shfl_xor_sync(0xffffffffu, ep[0], o);
            ep[1] += __shfl_xor_sync(0xffffffffu, ep[1], o);
        }
        if (cg == 0) { es[r0] = ep[0]; es[r0+1] = ep[1]; }
        __syncthreads();
        if (tid == 0) {
            float s = APM * aw_b2[0];
            #pragma unroll
            for (int a=0;a<APM;a++) s += es[a];
            out[(size_t)3*NATOMS + mol] = s;
        }
        // GEMM2h: gx = gp @ aw_W1^T -> Xs
        float acc2[2][4] = {};
        for (int k0=0;k0<FH;k0+=16) {
            __syncthreads();
            {
                int f = tid>>2, kq = (tid&3)<<2;
                float4 w = *(const float4*)&aw_W1[(size_t)f*FH + k0 + kq];
                Ws[(kq+0)*FDIM + f] = w.x;
                Ws[(kq+1)*FDIM + f] = w.y;
                Ws[(kq+2)*FDIM + f] = w.z;
                Ws[(kq+3)*FDIM + f] = w.w;
            }
            __syncthreads();
            #pragma unroll
            for (int kk=0;kk<16;kk++) {
                float a0 = Ts[r0*FH + k0+kk];
                float a1 = Ts[(r0+1)*FH + k0+kk];
                float4 b = *(float4*)&Ws[kk*FDIM + c0];
                acc2[0][0]=fmaf(a0,b.x,acc2[0][0]); acc2[0][1]=fmaf(a0,b.y,acc2[0][1]);
                acc2[0][2]=fmaf(a0,b.z,acc2[0][2]); acc2[0][3]=fmaf(a0,b.w,acc2[0][3]);
                acc2[1][0]=fmaf(a1,b.x,acc2[1][0]); acc2[1][1]=fmaf(a1,b.y,acc2[1][1]);
                acc2[1][2]=fmaf(a1,b.z,acc2[1][2]); acc2[1][3]=fmaf(a1,b.w,acc2[1][3]);
            }
        }
        __syncthreads();
        #pragma unroll
        for (int m=0;m<2;m++)
            *(float4*)&Xs[(r0+m)*FDIM + c0] =
                make_float4(acc2[m][0],acc2[m][1],acc2[m][2],acc2[m][3]);
    }

    // =============== backward layers ===============
    for (int l = NLAY-1; l >= 0; l--) {
        const float* W0 = in2f_W + (size_t)l*FDIM*FDIM;
        const float* W1 = f2_W1  + (size_t)l*FDIM*FDIM;
        const float* W2 = f2_W2  + (size_t)l*FDIM*FDIM;
        const float4* tW4 = tabW4g + (size_t)l*TABN*64;
        const float4* tD4 = tabD4g + (size_t)l*TABN*64;
        const float* s_g = g_sig2_ + (size_t)l*NF;

        if (l < 2) {   // Hs for l==2 persists from forward
            for (int t=tid; t<APM*FDIM/4; t+=512) {
                int a = t>>5, f4 = (t&31)<<2;
                *(float4*)&Hs[a*FDIM + f4] =
                    *(const float4*)&g_h_[(size_t)l*NF + (size_t)(abase+a)*FDIM + f4];
            }
        }

        float acc[2][4];
        // GEMM1: gpre2 = (gx @ W2^T) * sig2 -> Ts
        gemm128<true>(Xs, W2, Ws, tid, r0, c0, acc);
        #pragma unroll
        for (int m=0;m<2;m++) {
            float4 s4 = *(const float4*)&s_g[(size_t)(abase+r0+m)*FDIM + c0];
            Ts[(r0+m)*FDIM + c0 + 0] = acc[m][0]*s4.x;
            Ts[(r0+m)*FDIM + c0 + 1] = acc[m][1]*s4.y;
            Ts[(r0+m)*FDIM + c0 + 2] = acc[m][2]*s4.z;
            Ts[(r0+m)*FDIM + c0 + 3] = acc[m][3]*s4.w;
        }

        // GEMM2: ga = gpre2 @ W1^T -> As
        gemm128<true>(Ts, W1, Ws, tid, r0, c0, acc);
        #pragma unroll
        for (int m=0;m<2;m++)
            *(float4*)&As[(r0+m)*FDIM + c0] =
                make_float4(acc[m][0],acc[m][1],acc[m][2],acc[m][3]);
        __syncthreads();

        // gh phase: Ts[j][f] = sum over listJ[j]
        for (int jt=0; jt<4; jt++) {
            int j = jt*8 + er;
            int cnt = cntJ[j];
            ull accp = 0ull;
            for (int c=0;c<cnt;c++) {
                float2 e = liJ[j*31+c];
                float enc = e.y;
                int i = (int)(enc * (1.f/2048.f));
                float u = enc - (float)i*2048.f;
                int t0 = (int)u;
                float fr = u - (float)t0;
                ulonglong2 wv = *(const ulonglong2*)&tW4[((size_t)t0<<6) + f2];
                ull w01 = fma2(pk2(fr), wv.y, wv.x);
                ull ga = *(const ull*)&As[i*FDIM + 2*f2];
                accp = fma2(mul2(ga, pk2(e.x)), w01, accp);
            }
            *(ull*)&Ts[j*FDIM + 2*f2] = accp;
        }

        // gd phase: warp handles 2 rows of listI
        {
            const int warp = tid >> 5, lane = cg;
            #pragma unroll
            for (int rr=0; rr<2; rr++) {
                int i = warp*2 + rr;
                int cnt = cntI[i];
                for (int c=0;c<cnt;c++) {
                    float2 e = liI[i*31+c];
                    float fc = e.x;
                    float enc = e.y;
                    int j = (int)(enc * (1.f/2048.f));
                    float u = enc - (float)j*2048.f;
                    int t0 = (int)u;
                    float fr = u - (float)t0;
                    float cs = 2.f*fc - 1.f;
                    float dfc = -(0.5f*PI_F/CUT) * sqrtf(fmaxf(1.f - cs*cs, 0.f));
                    ull frp = pk2(fr);
                    ull sWp = 0ull, sDp = 0ull;
                    #pragma unroll
                    for (int hh=0; hh<2; hh++) {
                        int fp = hh*32 + lane;
                        ulonglong2 wv = *(const ulonglong2*)&tW4[((size_t)t0<<6) + fp];
                        ulonglong2 dv = *(const ulonglong2*)&tD4[((size_t)t0<<6) + fp];
                        ull ga = *(const ull*)&As[i*FDIM + 2*fp];
                        ull hv = *(const ull*)&Hs[j*FDIM + 2*fp];
                        ull p = mul2(ga, hv);
                        sWp = fma2(p, fma2(frp, wv.y, wv.x), sWp);
                        sDp = fma2(p, fma2(frp, dv.y, dv.x), sDp);
                    }
                    float2 aW = upk(sWp), aD = upk(sDp);
                    float term = fmaf(fc, aD.x + aD.y, dfc*(aW.x + aW.y));
                    #pragma unroll
                    for (int o=16;o>0;o>>=1)
                        term += __shfl_xor_sync(0xffffffffu, term, o);
                    if (lane == 0) gd_s[i*31+c] += term;
                }
            }
        }

        // GEMM3: gx += gh @ W0^T
        gemm128<true>(Ts, W0, Ws, tid, r0, c0, acc);
        #pragma unroll
        for (int m=0;m<2;m++) {
            float* gp = &Xs[(r0+m)*FDIM + c0];
            gp[0] += acc[m][0]; gp[1] += acc[m][1];
            gp[2] += acc[m][2]; gp[3] += acc[m][3];
        }
    }
    __syncthreads();

    // =============== action ===============
    {
        float* gp  = Ws;
        float* nrm = Ws + 96;
        float* cf  = Ws + 128;
        if (tid < 96) gp[tid] = 0.f;
        __syncthreads();
        for (int el=tid; el<APM*31; el+=512) {
            int i = el / 31, slot = el - i*31;
            if (slot < cntI[i]) {
                float2 e = liI[el];
                float enc = e.y;
                int j = (int)(enc * (1.f/2048.f));
                float u = enc - (float)j*2048.f;
                float d = u * (CUT/(float)(TABN-1));
                float g = gd_s[el] / d;
                float rx = pos_s[j*3+0]-pos_s[i*3+0];
                float ry = pos_s[j*3+1]-pos_s[i*3+1];
                float rz = pos_s[j*3+2]-pos_s[i*3+2];
                atomicAdd(&gp[j*3+0],  g*rx); atomicAdd(&gp[j*3+1],  g*ry);
                atomicAdd(&gp[j*3+2],  g*rz);
                atomicAdd(&gp[i*3+0], -g*rx); atomicAdd(&gp[i*3+1], -g*ry);
                atomicAdd(&gp[i*3+2], -g*rz);
            }
        }
        __syncthreads();
        if (tid < APM) {
            float ax = gp[tid*3+0], ay = gp[tid*3+1], az = gp[tid*3+2];
            nrm[tid] = sqrtf(ax*ax + ay*ay + az*az);
        }
        __syncthreads();
        if (tid == 0) {
            float mx = 0.f;
            #pragma unroll
            for (int a=0;a<APM;a++) mx = fmaxf(mx, nrm[a]);
            cf[0] = fminf(1.0f / fmaxf(mx, 1e-8f), 1.0f);
        }
        __syncthreads();
        float coef = cf[0];
        for (int t=tid; t<96; t+=512)
            out[(size_t)abase*3 + t] = -gp[t]*coef;
    }
}

// ---------------- host ----------------
static const int MEGA_SMEM = SM_FLOATS * 4;

extern "C" void kernel_launch(void* const* d_in, const int* in_sizes, int n_in,
                              void* d_out, int out_size)
{
    const float* positions = (const float*)d_in[0];
    const float* emb       = (const float*)d_in[1];
    const float* in2f_W    = (const float*)d_in[2];
    const float* filt_W1   = (const float*)d_in[3];
    const float* filt_b1   = (const float*)d_in[4];
    const float* filt_W2   = (const float*)d_in[5];
    const float* filt_b2   = (const float*)d_in[6];
    const float* f2_W1     = (const float*)d_in[7];
    const float* f2_b1     = (const float*)d_in[8];
    const float* f2_W2     = (const float*)d_in[9];
    const float* f2_b2     = (const float*)d_in[10];
    const float* aw_W1     = (const float*)d_in[11];
    const float* aw_b1     = (const float*)d_in[12];
    const float* aw_W2     = (const float*)d_in[13];
    const float* aw_b2     = (const float*)d_in[14];
    const int*   Z         = (const int*)d_in[15];
    float* out = (float*)d_out;

    float *p_h, *p_sig2, *p_tabW, *p_tabD;
    float4 *p_tabW4, *p_tabD4;
    cudaGetSymbolAddress((void**)&p_h,     g_h);
    cudaGetSymbolAddress((void**)&p_sig2,  g_sig2);
    cudaGetSymbolAddress((void**)&p_tabW,  g_tabW);
    cudaGetSymbolAddress((void**)&p_tabD,  g_tabD);
    cudaGetSymbolAddress((void**)&p_tabW4, g_tabW4);
    cudaGetSymbolAddress((void**)&p_tabD4, g_tabD4);

    cudaFuncSetAttribute(mega_k, cudaFuncAttributeMaxDynamicSharedMemorySize,
                         MEGA_SMEM);

    table_k<<<dim3(TABN,3),128>>>(filt_W1, filt_b1, filt_W2, filt_b2,
                                  p_tabW, p_tabD);
    interleave4_k<<<dim3(TABN,3),64>>>(p_tabW, p_tabD, p_tabW4, p_tabD4);
    mega_k<<<NMOL, 512, MEGA_SMEM>>>(
        positions, emb, Z, in2f_W,
        f2_W1, f2_b1, f2_W2, f2_b2,
        aw_W1, aw_b1, aw_W2, aw_b2,
        p_tabW4, p_tabD4, p_h, p_sig2, out);
}

// round 7
// speedup vs baseline: 9.0676x; 1.0387x over previous
#include <cuda_runtime.h>
#include <math.h>

// ---------------- problem constants ----------------
#define NATOMS 16384
#define NMOL   512
#define APM    32
#define FDIM   128
#define NRBF   20
#define FH     64
#define NLAY   3
#define PI_F   3.14159265358979f
#define CUT    5.0f
#define LOG2_F 0.6931471805599453f
#define TABN   1024

static const size_t NF = (size_t)NATOMS * FDIM;

typedef unsigned long long ull;

// ---------------- scratch ----------------
__device__ __align__(16) float  g_h    [2 * NF];
__device__ __align__(16) float  g_sig2 [3 * NF];
__device__ __align__(16) float  g_tabW [3 * TABN * FDIM];
__device__ __align__(16) float  g_tabD [3 * TABN * FDIM];
__device__ __align__(16) float4 g_tFW4 [3 * TABN * 64];   // fc*W   (v0,v1,s0,s1)
__device__ __align__(16) float4 g_tG4  [3 * TABN * 64];   // fc*D+dfc*W

__device__ __forceinline__ float sspf(float v) {
    return fmaxf(v, 0.f) + log1pf(expf(-fabsf(v))) - LOG2_F;
}
__device__ __forceinline__ ull pk2(float x) {
    ull r; asm("mov.b64 %0, {%1, %1};" : "=l"(r) : "f"(x)); return r;
}
__device__ __forceinline__ ull fma2(ull a, ull b, ull c) {
    ull d; asm("fma.rn.f32x2 %0, %1, %2, %3;" : "=l"(d) : "l"(a), "l"(b), "l"(c)); return d;
}
__device__ __forceinline__ ull mul2(ull a, ull b) {
    ull d; asm("mul.rn.f32x2 %0, %1, %2;" : "=l"(d) : "l"(a), "l"(b)); return d;
}
__device__ __forceinline__ float2 upk(ull v) {
    float2 r; asm("mov.b64 {%0, %1}, %2;" : "=f"(r.x), "=f"(r.y) : "l"(v)); return r;
}

// ---------------- filter table build (raw W, dW/dd) ----------------
__global__ __launch_bounds__(128) void table_k(
    const float* __restrict__ W1, const float* __restrict__ b1,
    const float* __restrict__ W2, const float* __restrict__ b2,
    float* __restrict__ tabW, float* __restrict__ tabD)
{
    const int t = blockIdx.x;
    const int l = blockIdx.y;
    const int f = threadIdx.x;
    const float DELTA = CUT / (NRBF-1);
    const float CO = -0.5f / (DELTA*DELTA);
    const float d = t * (CUT / (TABN-1));

    __shared__ float rbf_s[NRBF], drbf_s[NRBF];
    __shared__ float t1_s[FDIM], dt1_s[FDIM];
    if (f < NRBF) {
        float u = d - f*DELTA;
        float g = expf(CO*u*u);
        rbf_s[f]  = g;
        drbf_s[f] = g * (2.f*CO*u);
    }
    __syncthreads();

    const float* W1l = W1 + (size_t)l*NRBF*FDIM;
    float p = b1[l*FDIM + f], dp = 0.f;
    #pragma unroll
    for (int k=0;k<NRBF;k++) {
        float w = W1l[k*FDIM + f];
        p  = fmaf(rbf_s[k],  w, p);
        dp = fmaf(drbf_s[k], w, dp);
    }
    float sg = 1.f/(1.f+expf(-p));
    t1_s[f]  = sspf(p);
    dt1_s[f] = sg*dp;
    __syncthreads();

    const float* W2l = W2 + (size_t)l*FDIM*FDIM;
    float w = b2[l*FDIM + f], dw = 0.f;
    #pragma unroll 8
    for (int c=0;c<FDIM;c++) {
        float wv = W2l[c*FDIM + f];
        w  = fmaf(t1_s[c],  wv, w);
        dw = fmaf(dt1_s[c], wv, dw);
    }
    size_t o = ((size_t)l*TABN + t)*FDIM + f;
    tabW[o] = w;
    tabD[o] = dw;
}

__device__ __forceinline__ void fc_dfc(int t, float& fc, float& dfc) {
    float d = t * (CUT/(float)(TABN-1));
    float ang = PI_F * d * (1.f/CUT);
    fc  = 0.5f*(cosf(ang)+1.f);
    dfc = -(0.5f*PI_F/CUT)*sinf(ang);
}

// combined tables: FW = fc*W ; G = fc*D + dfc*W ; packed (v0,v1,s0,s1) per pair
__global__ __launch_bounds__(64) void combine4_k(
    const float* __restrict__ tabW, const float* __restrict__ tabD,
    float4* __restrict__ tFW4, float4* __restrict__ tG4)
{
    const int t = blockIdx.x, l = blockIdx.y, f = threadIdx.x; // pair 0..63
    size_t o  = ((size_t)l*TABN + t)*FDIM;
    size_t o4 = ((size_t)l*TABN + t)*64 + f;
    float fcA, dfcA, fcB, dfcB;
    fc_dfc(t, fcA, dfcA);
    int tB = (t < TABN-1) ? t+1 : t;
    fc_dfc(tB, fcB, dfcB);
    size_t oB = ((size_t)l*TABN + tB)*FDIM;

    float wA0 = tabW[o  + 2*f], wA1 = tabW[o  + 2*f + 1];
    float wB0 = tabW[oB + 2*f], wB1 = tabW[oB + 2*f + 1];
    float dA0 = tabD[o  + 2*f], dA1 = tabD[o  + 2*f + 1];
    float dB0 = tabD[oB + 2*f], dB1 = tabD[oB + 2*f + 1];

    float fwA0 = fcA*wA0, fwA1 = fcA*wA1;
    float fwB0 = fcB*wB0, fwB1 = fcB*wB1;
    tFW4[o4] = make_float4(fwA0, fwA1, fwB0 - fwA0, fwB1 - fwA1);

    float gA0 = fcA*dA0 + dfcA*wA0, gA1 = fcA*dA1 + dfcA*wA1;
    float gB0 = fcB*dB0 + dfcB*wB0, gB1 = fcB*dB1 + dfcB*wB1;
    tG4[o4] = make_float4(gA0, gA1, gB0 - gA0, gB1 - gA1);
}

// ---------------- GEMM: C(32x128) = A_s @ B, f32x2 + double-buffered weights ----
template<bool TRANSB>
__device__ __forceinline__ void ldW(float* Wd, const float* __restrict__ Bg,
                                    int k0, int tid)
{
    if (!TRANSB) {
        int row = tid>>5, c4 = (tid&31)<<2;
        *(float4*)&Wd[row*FDIM + c4] =
            *(const float4*)&Bg[(size_t)(k0+row)*FDIM + c4];
    } else {
        int c = tid>>2, kq = (tid&3)<<2;
        float4 w = *(const float4*)&Bg[(size_t)c*FDIM + k0 + kq];
        Wd[(kq+0)*FDIM + c] = w.x;
        Wd[(kq+1)*FDIM + c] = w.y;
        Wd[(kq+2)*FDIM + c] = w.z;
        Wd[(kq+3)*FDIM + c] = w.w;
    }
}

template<bool TRANSB>
__device__ __forceinline__ void gemm128(const float* __restrict__ A_s,
                                        const float* __restrict__ Bg,
                                        float* Ws, int tid, int r0, int c0,
                                        float out[2][4])
{
    ull acc00=0ull, acc01=0ull, acc10=0ull, acc11=0ull;
    ldW<TRANSB>(Ws, Bg, 0, tid);
    __syncthreads();
    for (int ch=0; ch<8; ch++) {
        const float* Wc = Ws + (ch&1)*2048;
        if (ch < 7) ldW<TRANSB>(Ws + ((ch+1)&1)*2048, Bg, (ch+1)*16, tid);
        const int k0 = ch*16;
        #pragma unroll
        for (int kk=0;kk<16;kk++) {
            ull a0p = pk2(A_s[r0*FDIM + k0+kk]);
            ull a1p = pk2(A_s[(r0+1)*FDIM + k0+kk]);
            ulonglong2 bp = *(const ulonglong2*)&Wc[kk*FDIM + c0];
            acc00 = fma2(a0p, bp.x, acc00);
            acc01 = fma2(a0p, bp.y, acc01);
            acc10 = fma2(a1p, bp.x, acc10);
            acc11 = fma2(a1p, bp.y, acc11);
        }
        __syncthreads();
    }
    float2 v;
    v = upk(acc00); out[0][0]=v.x; out[0][1]=v.y;
    v = upk(acc01); out[0][2]=v.x; out[0][3]=v.y;
    v = upk(acc10); out[1][0]=v.x; out[1][1]=v.y;
    v = upk(acc11); out[1][2]=v.x; out[1][3]=v.y;
}

// ---------------- smem pool (floats) ----------------
#define OFF_XS   0
#define OFF_HS   (OFF_XS + APM*FDIM)
#define OFF_AS   (OFF_HS + APM*FDIM)
#define OFF_TS   (OFF_AS + APM*FDIM)
#define OFF_WS   (OFF_TS + APM*FDIM)        // 2 x 2048
#define OFF_LI   (OFF_WS + 4096)            // float[APM*31]
#define OFF_LJ   (OFF_LI + APM*31)
#define OFF_GD   (OFF_LJ + APM*31)
#define OFF_POS  (OFF_GD + APM*31)
#define OFF_CNT  (OFF_POS + 96)             // int[64]
#define OFF_ES   (OFF_CNT + 64)
#define SM_FLOATS (OFF_ES + 32)

__global__ __launch_bounds__(512,2) void mega_k(
    const float* __restrict__ pos, const float* __restrict__ emb,
    const int* __restrict__ Z,
    const float* __restrict__ in2f_W,
    const float* __restrict__ f2_W1, const float* __restrict__ f2_b1,
    const float* __restrict__ f2_W2, const float* __restrict__ f2_b2,
    const float* __restrict__ aw_W1, const float* __restrict__ aw_b1,
    const float* __restrict__ aw_W2, const float* __restrict__ aw_b2,
    const float4* __restrict__ tFW4g, const float4* __restrict__ tG4g,
    float* __restrict__ g_h_, float* __restrict__ g_sig2_,
    float* __restrict__ out)
{
    extern __shared__ float sm[];
    float*  Xs    = sm + OFF_XS;
    float*  Hs    = sm + OFF_HS;
    float*  As    = sm + OFF_AS;
    float*  Ts    = sm + OFF_TS;
    float*  Ws    = sm + OFF_WS;
    float*  liI   = sm + OFF_LI;
    float*  liJ   = sm + OFF_LJ;
    float*  gd_s  = sm + OFF_GD;
    float*  pos_s = sm + OFF_POS;
    int*    cntI  = (int*)(sm + OFF_CNT);
    int*    cntJ  = cntI + 32;
    float*  es    = sm + OFF_ES;

    const int tid = threadIdx.x;
    const int mol = blockIdx.x;
    const int abase = mol*APM;

    const int rg = tid>>5, cg = tid&31;
    const int r0 = rg<<1, c0 = cg<<2;
    const int f2 = tid & 63, er = tid >> 6;

    // ---------- P0: pos, gather x, zero gd ----------
    if (tid < 96) pos_s[tid] = pos[abase*3 + tid];
    for (int t=tid; t<APM*FDIM/4; t+=512) {
        int a = t>>5, f4 = (t&31)<<2;
        int z = Z[abase + a];
        *(float4*)&Xs[a*FDIM + f4] = *(const float4*)&emb[(size_t)z*FDIM + f4];
    }
    for (int t=tid; t<APM*31; t+=512) gd_s[t] = 0.f;
    __syncthreads();

    // ---------- P0b: build compacted edge lists ----------
    if (tid < 64) {
        const int role = tid >> 5;      // 0: by-i, 1: by-j
        const int a = tid & 31;
        int count = 0;
        for (int c=0; c<31; c++) {
            int other = c + (c >= a ? 1 : 0);
            int i = role==0 ? a : other;
            int j = role==0 ? other : a;
            float rx = pos_s[j*3+0]-pos_s[i*3+0];
            float ry = pos_s[j*3+1]-pos_s[i*3+1];
            float rz = pos_s[j*3+2]-pos_s[i*3+2];
            float d = sqrtf(rx*rx+ry*ry+rz*rz + 1e-12f);
            if (d < CUT) {
                float u = fminf(fmaxf(d*((float)(TABN-1)/CUT), 0.01f),
                                (float)(TABN-2) + 0.999f);
                float enc = (float)other*2048.f + u;
                if (role==0) liI[a*31+count] = enc;
                else         liJ[a*31+count] = enc;
                count++;
            }
        }
        if (role==0) cntI[a] = count; else cntJ[a] = count;
    }
    __syncthreads();

    // =============== forward layers ===============
    for (int l = 0; l < NLAY; l++) {
        const float* W0 = in2f_W + (size_t)l*FDIM*FDIM;
        const float* W1 = f2_W1  + (size_t)l*FDIM*FDIM;
        const float* W2 = f2_W2  + (size_t)l*FDIM*FDIM;
        const float4* tFW = tFW4g + (size_t)l*TABN*64;
        float* s_g = g_sig2_ + (size_t)l*NF;

        float acc[2][4];
        // GEMM1: h = x @ W0
        gemm128<false>(Xs, W0, Ws, tid, r0, c0, acc);
        #pragma unroll
        for (int m=0;m<2;m++) {
            float4 v = make_float4(acc[m][0],acc[m][1],acc[m][2],acc[m][3]);
            *(float4*)&Hs[(r0+m)*FDIM + c0] = v;
            if (l < 2)
                *(float4*)&g_h_[(size_t)l*NF + (size_t)(abase+r0+m)*FDIM + c0] = v;
        }
        __syncthreads();

        // agg: As[i] = sum_j h[j] .* FW(d_ij)
        for (int it=0; it<4; it++) {
            int i = it*8 + er;
            int cnt = cntI[i];
            ull accp = 0ull;
            #pragma unroll 2
            for (int c=0;c<cnt;c++) {
                float enc = liI[i*31+c];
                int j = (int)(enc * (1.f/2048.f));
                float u = enc - (float)j*2048.f;
                int t0 = (int)u;
                float fr = u - (float)t0;
                ulonglong2 wv = *(const ulonglong2*)&tFW[((size_t)t0<<6) + f2];
                ull w01 = fma2(pk2(fr), wv.y, wv.x);
                ull h01 = *(const ull*)&Hs[j*FDIM + 2*f2];
                accp = fma2(h01, w01, accp);
            }
            *(ull*)&As[i*FDIM + 2*f2] = accp;
        }

        // GEMM2: pre = agg@W1 + b1; sig2->global; t2=ssp->Ts
        gemm128<false>(As, W1, Ws, tid, r0, c0, acc);
        {
            float4 b1v = *(const float4*)&f2_b1[l*FDIM + c0];
            float bb[4]={b1v.x,b1v.y,b1v.z,b1v.w};
            #pragma unroll
            for (int m=0;m<2;m++) {
                float sg4[4];
                #pragma unroll
                for (int n=0;n<4;n++) {
                    float pre = acc[m][n] + bb[n];
                    sg4[n] = 1.f/(1.f+expf(-pre));
                    Ts[(r0+m)*FDIM + c0 + n] = sspf(pre);
                }
                *(float4*)&s_g[(size_t)(abase+r0+m)*FDIM + c0] =
                    make_float4(sg4[0],sg4[1],sg4[2],sg4[3]);
            }
        }

        // GEMM3: x += t2@W2 + b2
        gemm128<false>(Ts, W2, Ws, tid, r0, c0, acc);
        {
            float4 b2v = *(const float4*)&f2_b2[l*FDIM + c0];
            #pragma unroll
            for (int m=0;m<2;m++) {
                float* xp = &Xs[(r0+m)*FDIM + c0];
                xp[0] += acc[m][0] + b2v.x;
                xp[1] += acc[m][1] + b2v.y;
                xp[2] += acc[m][2] + b2v.z;
                xp[3] += acc[m][3] + b2v.w;
            }
        }
    }

    // =============== head: fwd + bwd ===============
    {
        if (tid < APM) es[tid] = 0.f;
        const int hc0 = cg<<1;
        float acc[2][2] = {};
        for (int k0=0;k0<FDIM;k0+=16) {
            __syncthreads();
            if (tid < 256) {
                int row = tid>>4, c4 = (tid&15)<<2;
                *(float4*)&Ws[row*FH + c4] =
                    *(const float4*)&aw_W1[(size_t)(k0+row)*FH + c4];
            }
            __syncthreads();
            #pragma unroll
            for (int kk=0;kk<16;kk++) {
                float a0 = Xs[r0*FDIM + k0+kk];
                float a1 = Xs[(r0+1)*FDIM + k0+kk];
                float2 b = *(float2*)&Ws[kk*FH + hc0];
                acc[0][0]=fmaf(a0,b.x,acc[0][0]); acc[0][1]=fmaf(a0,b.y,acc[0][1]);
                acc[1][0]=fmaf(a1,b.x,acc[1][0]); acc[1][1]=fmaf(a1,b.y,acc[1][1]);
            }
        }
        float2 b1v = *(const float2*)&aw_b1[hc0];
        float2 w2v = *(const float2*)&aw_W2[hc0];
        float ep[2];
        #pragma unroll
        for (int m=0;m<2;m++) {
            float pre0 = acc[m][0] + b1v.x;
            float pre1 = acc[m][1] + b1v.y;
            float sg0 = 1.f/(1.f+expf(-pre0));
            float sg1 = 1.f/(1.f+expf(-pre1));
            ep[m] = sspf(pre0)*w2v.x + sspf(pre1)*w2v.y;
            Ts[(r0+m)*FH + hc0 + 0] = sg0*w2v.x;
            Ts[(r0+m)*FH + hc0 + 1] = sg1*w2v.y;
        }
        #pragma unroll
        for (int o=16;o>0;o>>=1) {
            ep[0] += __shfl_xor_sync(0xffffffffu, ep[0], o);
            ep[1] += __shfl_xor_sync(0xffffffffu, ep[1], o);
        }
        if (cg == 0) { es[r0] = ep[0]; es[r0+1] = ep[1]; }
        __syncthreads();
        if (tid == 0) {
            float s = APM * aw_b2[0];
            #pragma unroll
            for (int a=0;a<APM;a++) s += es[a];
            out[(size_t)3*NATOMS + mol] = s;
        }
        // GEMM2h: gx = gp @ aw_W1^T -> Xs
        float acc2[2][4] = {};
        for (int k0=0;k0<FH;k0+=16) {
            __syncthreads();
            {
                int f = tid>>2, kq = (tid&3)<<2;
                float4 w = *(const float4*)&aw_W1[(size_t)f*FH + k0 + kq];
                Ws[(kq+0)*FDIM + f] = w.x;
                Ws[(kq+1)*FDIM + f] = w.y;
                Ws[(kq+2)*FDIM + f] = w.z;
                Ws[(kq+3)*FDIM + f] = w.w;
            }
            __syncthreads();
            #pragma unroll
            for (int kk=0;kk<16;kk++) {
                float a0 = Ts[r0*FH + k0+kk];
                float a1 = Ts[(r0+1)*FH + k0+kk];
                float4 b = *(float4*)&Ws[kk*FDIM + c0];
                acc2[0][0]=fmaf(a0,b.x,acc2[0][0]); acc2[0][1]=fmaf(a0,b.y,acc2[0][1]);
                acc2[0][2]=fmaf(a0,b.z,acc2[0][2]); acc2[0][3]=fmaf(a0,b.w,acc2[0][3]);
                acc2[1][0]=fmaf(a1,b.x,acc2[1][0]); acc2[1][1]=fmaf(a1,b.y,acc2[1][1]);
                acc2[1][2]=fmaf(a1,b.z,acc2[1][2]); acc2[1][3]=fmaf(a1,b.w,acc2[1][3]);
            }
        }
        __syncthreads();
        #pragma unroll
        for (int m=0;m<2;m++)
            *(float4*)&Xs[(r0+m)*FDIM + c0] =
                make_float4(acc2[m][0],acc2[m][1],acc2[m][2],acc2[m][3]);
    }

    // =============== backward layers ===============
    for (int l = NLAY-1; l >= 0; l--) {
        const float* W0 = in2f_W + (size_t)l*FDIM*FDIM;
        const float* W1 = f2_W1  + (size_t)l*FDIM*FDIM;
        const float* W2 = f2_W2  + (size_t)l*FDIM*FDIM;
        const float4* tFW = tFW4g + (size_t)l*TABN*64;
        const float4* tG  = tG4g  + (size_t)l*TABN*64;
        const float* s_g = g_sig2_ + (size_t)l*NF;

        if (l < 2) {   // Hs for l==2 persists from forward
            for (int t=tid; t<APM*FDIM/4; t+=512) {
                int a = t>>5, f4 = (t&31)<<2;
                *(float4*)&Hs[a*FDIM + f4] =
                    *(const float4*)&g_h_[(size_t)l*NF + (size_t)(abase+a)*FDIM + f4];
            }
        }

        float acc[2][4];
        // GEMM1: gpre2 = (gx @ W2^T) * sig2 -> Ts
        gemm128<true>(Xs, W2, Ws, tid, r0, c0, acc);
        #pragma unroll
        for (int m=0;m<2;m++) {
            float4 s4 = *(const float4*)&s_g[(size_t)(abase+r0+m)*FDIM + c0];
            Ts[(r0+m)*FDIM + c0 + 0] = acc[m][0]*s4.x;
            Ts[(r0+m)*FDIM + c0 + 1] = acc[m][1]*s4.y;
            Ts[(r0+m)*FDIM + c0 + 2] = acc[m][2]*s4.z;
            Ts[(r0+m)*FDIM + c0 + 3] = acc[m][3]*s4.w;
        }

        // GEMM2: ga = gpre2 @ W1^T -> As
        gemm128<true>(Ts, W1, Ws, tid, r0, c0, acc);
        #pragma unroll
        for (int m=0;m<2;m++)
            *(float4*)&As[(r0+m)*FDIM + c0] =
                make_float4(acc[m][0],acc[m][1],acc[m][2],acc[m][3]);
        __syncthreads();

        // gh phase: Ts[j] = sum_i ga[i] .* FW(d_ij)
        for (int jt=0; jt<4; jt++) {
            int j = jt*8 + er;
            int cnt = cntJ[j];
            ull accp = 0ull;
            #pragma unroll 2
            for (int c=0;c<cnt;c++) {
                float enc = liJ[j*31+c];
                int i = (int)(enc * (1.f/2048.f));
                float u = enc - (float)i*2048.f;
                int t0 = (int)u;
                float fr = u - (float)t0;
                ulonglong2 wv = *(const ulonglong2*)&tFW[((size_t)t0<<6) + f2];
                ull w01 = fma2(pk2(fr), wv.y, wv.x);
                ull ga = *(const ull*)&As[i*FDIM + 2*f2];
                accp = fma2(ga, w01, accp);
            }
            *(ull*)&Ts[j*FDIM + 2*f2] = accp;
        }

        // gd phase: warp-per-edge, single combined table G
        {
            const int warp = tid >> 5, lane = cg;
            #pragma unroll
            for (int rr=0; rr<2; rr++) {
                int i = warp*2 + rr;
                int cnt = cntI[i];
                #pragma unroll 2
                for (int c=0;c<cnt;c++) {
                    float enc = liI[i*31+c];
                    int j = (int)(enc * (1.f/2048.f));
                    float u = enc - (float)j*2048.f;
                    int t0 = (int)u;
                    ull frp = pk2(u - (float)t0);
                    const float4* tg = tG + ((size_t)t0<<6);
                    ull s = 0ull;
                    #pragma unroll
                    for (int hh=0; hh<2; hh++) {
                        int fp = hh*32 + lane;
                        ulonglong2 gv = *(const ulonglong2*)&tg[fp];
                        ull ga = *(const ull*)&As[i*FDIM + 2*fp];
                        ull hv = *(const ull*)&Hs[j*FDIM + 2*fp];
                        s = fma2(mul2(ga, hv), fma2(frp, gv.y, gv.x), s);
                    }
                    float2 sv = upk(s);
                    float term = sv.x + sv.y;
                    #pragma unroll
                    for (int o=16;o>0;o>>=1)
                        term += __shfl_xor_sync(0xffffffffu, term, o);
                    if (lane == 0) gd_s[i*31+c] += term;
                }
            }
        }

        // GEMM3: gx += gh @ W0^T
        gemm128<true>(Ts, W0, Ws, tid, r0, c0, acc);
        #pragma unroll
        for (int m=0;m<2;m++) {
            float* gp = &Xs[(r0+m)*FDIM + c0];
            gp[0] += acc[m][0]; gp[1] += acc[m][1];
            gp[2] += acc[m][2]; gp[3] += acc[m][3];
        }
    }
    __syncthreads();

    // =============== action ===============
    {
        float* gp  = Ws;
        float* nrm = Ws + 96;
        float* cf  = Ws + 128;
        if (tid < 96) gp[tid] = 0.f;
        __syncthreads();
        for (int el=tid; el<APM*31; el+=512) {
            int i = el / 31, slot = el - i*31;
            if (slot < cntI[i]) {
                float enc = liI[el];
                int j = (int)(enc * (1.f/2048.f));
                float u = enc - (float)j*2048.f;
                float d = u * (CUT/(float)(TABN-1));
                float g = gd_s[el] / d;
                float rx = pos_s[j*3+0]-pos_s[i*3+0];
                float ry = pos_s[j*3+1]-pos_s[i*3+1];
                float rz = pos_s[j*3+2]-pos_s[i*3+2];
                atomicAdd(&gp[j*3+0],  g*rx); atomicAdd(&gp[j*3+1],  g*ry);
                atomicAdd(&gp[j*3+2],  g*rz);
                atomicAdd(&gp[i*3+0], -g*rx); atomicAdd(&gp[i*3+1], -g*ry);
                atomicAdd(&gp[i*3+2], -g*rz);
            }
        }
        __syncthreads();
        if (tid < APM) {
            float ax = gp[tid*3+0], ay = gp[tid*3+1], az = gp[tid*3+2];
            nrm[tid] = sqrtf(ax*ax + ay*ay + az*az);
        }
        __syncthreads();
        if (tid == 0) {
            float mx = 0.f;
            #pragma unroll
            for (int a=0;a<APM;a++) mx = fmaxf(mx, nrm[a]);
            cf[0] = fminf(1.0f / fmaxf(mx, 1e-8f), 1.0f);
        }
        __syncthreads();
        float coef = cf[0];
        for (int t=tid; t<96; t+=512)
            out[(size_t)abase*3 + t] = -gp[t]*coef;
    }
}

// ---------------- host ----------------
static const int MEGA_SMEM = SM_FLOATS * 4;

extern "C" void kernel_launch(void* const* d_in, const int* in_sizes, int n_in,
                              void* d_out, int out_size)
{
    const float* positions = (const float*)d_in[0];
    const float* emb       = (const float*)d_in[1];
    const float* in2f_W    = (const float*)d_in[2];
    const float* filt_W1   = (const float*)d_in[3];
    const float* filt_b1   = (const float*)d_in[4];
    const float* filt_W2   = (const float*)d_in[5];
    const float* filt_b2   = (const float*)d_in[6];
    const float* f2_W1     = (const float*)d_in[7];
    const float* f2_b1     = (const float*)d_in[8];
    const float* f2_W2     = (const float*)d_in[9];
    const float* f2_b2     = (const float*)d_in[10];
    const float* aw_W1     = (const float*)d_in[11];
    const float* aw_b1     = (const float*)d_in[12];
    const float* aw_W2     = (const float*)d_in[13];
    const float* aw_b2     = (const float*)d_in[14];
    const int*   Z         = (const int*)d_in[15];
    float* out = (float*)d_out;

    float *p_h, *p_sig2, *p_tabW, *p_tabD;
    float4 *p_tFW4, *p_tG4;
    cudaGetSymbolAddress((void**)&p_h,     g_h);
    cudaGetSymbolAddress((void**)&p_sig2,  g_sig2);
    cudaGetSymbolAddress((void**)&p_tabW,  g_tabW);
    cudaGetSymbolAddress((void**)&p_tabD,  g_tabD);
    cudaGetSymbolAddress((void**)&p_tFW4,  g_tFW4);
    cudaGetSymbolAddress((void**)&p_tG4,   g_tG4);

    cudaFuncSetAttribute(mega_k, cudaFuncAttributeMaxDynamicSharedMemorySize,
                         MEGA_SMEM);

    table_k<<<dim3(TABN,3),128>>>(filt_W1, filt_b1, filt_W2, filt_b2,
                                  p_tabW, p_tabD);
    combine4_k<<<dim3(TABN,3),64>>>(p_tabW, p_tabD, p_tFW4, p_tG4);
    mega_k<<<NMOL, 512, MEGA_SMEM>>>(
        positions, emb, Z, in2f_W,
        f2_W1, f2_b1, f2_W2, f2_b2,
        aw_W1, aw_b1, aw_W2, aw_b2,
        p_tFW4, p_tG4, p_h, p_sig2, out);
}